// round 1
// baseline (speedup 1.0000x reference)
#include <cuda_runtime.h>
#include <cuda_bf16.h>
#include <math.h>

// ---- fixed problem shape (from reference) ----
#define NUM_ITEMS 50000
#define NUM_USERS 16384
#define H0 512
#define LAT 256
#define NMAX 262144

// ---- scratch (__device__ globals; no allocation allowed) ----
static __device__ float  g_WencT[(size_t)NUM_ITEMS * H0];   // [items, H0]
static __device__ float  g_x[(size_t)NUM_USERS * H0];
static __device__ float  g_enc[(size_t)NUM_USERS * LAT];
static __device__ float  g_dec[(size_t)NUM_USERS * H0];
static __device__ int    g_cnt[NUM_USERS];
static __device__ int    g_off[NUM_USERS + 1];
static __device__ int    g_cur[NUM_USERS];
static __device__ int    g_pitem[NMAX];
static __device__ float  g_prate[NMAX];
static __device__ double g_loss;

// ---------------- zero ----------------
__global__ void k_zero() {
    int i = blockIdx.x * blockDim.x + threadIdx.x;
    if (i < NUM_USERS) g_cnt[i] = 0;
    if (i == 0) g_loss = 0.0;
}

// ---------------- transpose W_enc [H0, NUM_ITEMS] -> g_WencT [NUM_ITEMS, H0] ----------------
__global__ void k_transpose(const float* __restrict__ W) {
    __shared__ float tile[32][33];
    int tx = threadIdx.x, ty = threadIdx.y;               // blockDim (32, 8)
    int col0 = blockIdx.x * 32;                           // item base
    int row0 = blockIdx.y * 32;                           // h base
    #pragma unroll
    for (int j = 0; j < 4; j++) {
        int r = ty + j * 8;
        int c = col0 + tx;
        if (c < NUM_ITEMS)
            tile[r][tx] = W[(size_t)(row0 + r) * NUM_ITEMS + c];
    }
    __syncthreads();
    #pragma unroll
    for (int j = 0; j < 4; j++) {
        int i = col0 + ty + j * 8;                         // item
        int h = row0 + tx;                                 // h
        if (i < NUM_ITEMS)
            g_WencT[(size_t)i * H0 + h] = tile[tx][ty + j * 8];
    }
}

// ---------------- histogram ----------------
__global__ void k_hist(const int* __restrict__ user, int n) {
    int i = blockIdx.x * blockDim.x + threadIdx.x;
    if (i < n) atomicAdd(&g_cnt[user[i]], 1);
}

// ---------------- exclusive scan over 16384 counts (one block) ----------------
__global__ void k_scan(int ntotal) {
    __shared__ int sh[1024];
    int t = threadIdx.x;                                   // 1024 threads
    int base = t * 16;
    int local[16];
    int s = 0;
    #pragma unroll
    for (int i = 0; i < 16; i++) { local[i] = g_cnt[base + i]; s += local[i]; }
    sh[t] = s;
    __syncthreads();
    for (int off = 1; off < 1024; off <<= 1) {
        int v = 0;
        if (t >= off) v = sh[t - off];
        __syncthreads();
        if (t >= off) sh[t] += v;
        __syncthreads();
    }
    int run = (t == 0) ? 0 : sh[t - 1];
    #pragma unroll
    for (int i = 0; i < 16; i++) {
        g_off[base + i] = run;
        g_cur[base + i] = run;
        run += local[i];
    }
    if (t == 1023) g_off[NUM_USERS] = run;                 // == ntotal
}

// ---------------- scatter (counting sort payloads) ----------------
__global__ void k_scatter(const int* __restrict__ user, const int* __restrict__ item,
                          const float* __restrict__ rating, int n) {
    int i = blockIdx.x * blockDim.x + threadIdx.x;
    if (i < n) {
        int p = atomicAdd(&g_cur[user[i]], 1);
        g_pitem[p] = item[i];
        g_prate[p] = rating[i];
    }
}

// ---------------- per-user encoder aggregation + tanh(+b_enc) ----------------
__global__ void k_encode(const float* __restrict__ b_enc) {
    int u = blockIdx.x;
    int t = threadIdx.x;                                   // 128 threads, float4 lanes
    int s = g_off[u], e = g_off[u + 1];
    const float4* WT4 = (const float4*)g_WencT;
    float4 acc = make_float4(0.f, 0.f, 0.f, 0.f);
    __shared__ int   sit[128];
    __shared__ float srt[128];
    for (int j0 = s; j0 < e; j0 += 128) {
        int c = min(128, e - j0);
        if (t < c) { sit[t] = g_pitem[j0 + t]; srt[t] = g_prate[j0 + t]; }
        __syncthreads();
        for (int q = 0; q < c; q++) {
            int it = sit[q]; float r = srt[q];
            float4 w = WT4[(size_t)it * 128 + t];
            acc.x = fmaf(r, w.x, acc.x);
            acc.y = fmaf(r, w.y, acc.y);
            acc.z = fmaf(r, w.z, acc.z);
            acc.w = fmaf(r, w.w, acc.w);
        }
        __syncthreads();
    }
    float4 b = ((const float4*)b_enc)[t];
    float4 xv;
    xv.x = tanhf(acc.x + b.x);
    xv.y = tanhf(acc.y + b.y);
    xv.z = tanhf(acc.z + b.z);
    xv.w = tanhf(acc.w + b.w);
    ((float4*)g_x)[(size_t)u * 128 + t] = xv;
}

// ---------------- GEMM: C[M,N] = tanh(A[M,K] @ B[N,K]^T + bias[N]) ----------------
// 128x128 tile, BK=8, 256 threads, 8x8 micro-tile (2x2 quadrants of 4).
__global__ void k_gemm_bias_tanh(const float* __restrict__ A, const float* __restrict__ B,
                                 const float* __restrict__ bias, float* __restrict__ C,
                                 int M, int Nn, int Kk) {
    __shared__ float As[8][128];
    __shared__ float Bs[8][128];
    int tid = threadIdx.x;
    int tx = tid % 16, ty = tid / 16;
    int bm = blockIdx.y * 128;
    int bn = blockIdx.x * 128;
    int lr  = tid >> 1;            // 0..127
    int lk4 = (tid & 1) * 4;       // 0 or 4

    float acc[8][8];
    #pragma unroll
    for (int i = 0; i < 8; i++)
        #pragma unroll
        for (int j = 0; j < 8; j++) acc[i][j] = 0.f;

    for (int k0 = 0; k0 < Kk; k0 += 8) {
        float4 a4 = *(const float4*)&A[(size_t)(bm + lr) * Kk + k0 + lk4];
        float4 b4 = *(const float4*)&B[(size_t)(bn + lr) * Kk + k0 + lk4];
        As[lk4 + 0][lr] = a4.x; As[lk4 + 1][lr] = a4.y;
        As[lk4 + 2][lr] = a4.z; As[lk4 + 3][lr] = a4.w;
        Bs[lk4 + 0][lr] = b4.x; Bs[lk4 + 1][lr] = b4.y;
        Bs[lk4 + 2][lr] = b4.z; Bs[lk4 + 3][lr] = b4.w;
        __syncthreads();
        #pragma unroll
        for (int k = 0; k < 8; k++) {
            float4 a0 = *(const float4*)&As[k][ty * 4];
            float4 a1 = *(const float4*)&As[k][ty * 4 + 64];
            float4 b0 = *(const float4*)&Bs[k][tx * 4];
            float4 b1 = *(const float4*)&Bs[k][tx * 4 + 64];
            float ra[8] = {a0.x, a0.y, a0.z, a0.w, a1.x, a1.y, a1.z, a1.w};
            float rb[8] = {b0.x, b0.y, b0.z, b0.w, b1.x, b1.y, b1.z, b1.w};
            #pragma unroll
            for (int i = 0; i < 8; i++)
                #pragma unroll
                for (int j = 0; j < 8; j++)
                    acc[i][j] = fmaf(ra[i], rb[j], acc[i][j]);
        }
        __syncthreads();
    }
    #pragma unroll
    for (int i = 0; i < 8; i++) {
        int m = bm + ty * 4 + ((i < 4) ? i : 60 + i);      // i>=4 -> 64 + (i-4)
        #pragma unroll
        for (int j = 0; j < 8; j++) {
            int n = bn + tx * 4 + ((j < 4) ? j : 60 + j);
            C[(size_t)m * Nn + n] = tanhf(acc[i][j] + bias[n]);
        }
    }
}

// ---------------- decoder: pred + MSE partials ----------------
__global__ void k_decode(const int* __restrict__ tuser, const int* __restrict__ titem,
                         const float* __restrict__ trating, const float* __restrict__ Wdec,
                         const float* __restrict__ bdec, float* __restrict__ out, int nt) {
    int warp = threadIdx.x >> 5, lane = threadIdx.x & 31;
    int t = blockIdx.x * 8 + warp;
    __shared__ double part[8];
    double mine = 0.0;
    if (t < nt) {
        int u = tuser[t], it = titem[t];
        const float4* g = (const float4*)g_dec + (size_t)u * 128;
        const float4* w = (const float4*)Wdec + (size_t)it * 128;
        float s = 0.f;
        #pragma unroll
        for (int q = 0; q < 4; q++) {
            float4 a = g[q * 32 + lane];
            float4 b = w[q * 32 + lane];
            s = fmaf(a.x, b.x, s);
            s = fmaf(a.y, b.y, s);
            s = fmaf(a.z, b.z, s);
            s = fmaf(a.w, b.w, s);
        }
        #pragma unroll
        for (int o = 16; o; o >>= 1) s += __shfl_xor_sync(0xffffffff, s, o);
        if (lane == 0) {
            float pred = s + bdec[it];
            out[t] = pred;
            float d = pred - trating[t];
            mine = (double)d * (double)d;
        }
    }
    if (lane == 0) part[warp] = mine;
    __syncthreads();
    if (threadIdx.x == 0) {
        double ss = 0.0;
        #pragma unroll
        for (int i = 0; i < 8; i++) ss += part[i];
        atomicAdd(&g_loss, ss);
    }
}

__global__ void k_final(float* out, int nt, int write_loss) {
    if (write_loss) out[nt] = (float)(g_loss / (double)nt);
}

// ---------------- launch ----------------
extern "C" void kernel_launch(void* const* d_in, const int* in_sizes, int n_in,
                              void* d_out, int out_size) {
    const int*   user    = (const int*)d_in[0];
    const int*   item    = (const int*)d_in[1];
    const float* rating  = (const float*)d_in[2];
    const int*   tuser   = (const int*)d_in[3];
    const int*   titem   = (const int*)d_in[4];
    const float* trating = (const float*)d_in[5];
    const float* W_enc   = (const float*)d_in[6];
    const float* b_enc   = (const float*)d_in[7];
    const float* W1      = (const float*)d_in[8];
    const float* b1      = (const float*)d_in[9];
    const float* W2      = (const float*)d_in[10];
    const float* b2      = (const float*)d_in[11];
    const float* W_dec   = (const float*)d_in[12];
    const float* b_dec   = (const float*)d_in[13];
    float* out = (float*)d_out;

    int N  = in_sizes[0];
    int NT = in_sizes[3];

    float* xp   = nullptr;  // device globals used directly inside kernels
    (void)xp; (void)n_in;

    // 1. zero counters + loss
    k_zero<<<(NUM_USERS + 255) / 256, 256>>>();
    // 2. transpose W_enc
    {
        dim3 b(32, 8), g((NUM_ITEMS + 31) / 32, H0 / 32);
        k_transpose<<<g, b>>>(W_enc);
    }
    // 3. counting sort by user
    k_hist<<<(N + 255) / 256, 256>>>(user, N);
    k_scan<<<1, 1024>>>(N);
    k_scatter<<<(N + 255) / 256, 256>>>(user, item, rating, N);
    // 4. per-user encoder aggregation + tanh
    k_encode<<<NUM_USERS, 128>>>(b_enc);
    // 5. MLP: encoded = tanh(x @ W1^T + b1)
    {
        float* enc_ptr; cudaGetSymbolAddress((void**)&enc_ptr, g_enc);
        float* x_ptr;   cudaGetSymbolAddress((void**)&x_ptr, g_x);
        dim3 g(LAT / 128, NUM_USERS / 128);
        k_gemm_bias_tanh<<<g, 256>>>(x_ptr, W1, b1, enc_ptr, NUM_USERS, LAT, H0);
        // 6. decoded = tanh(encoded @ W2^T + b2)
        float* dec_ptr; cudaGetSymbolAddress((void**)&dec_ptr, g_dec);
        dim3 g2(H0 / 128, NUM_USERS / 128);
        k_gemm_bias_tanh<<<g2, 256>>>(enc_ptr, W2, b2, dec_ptr, NUM_USERS, H0, LAT);
    }
    // 7. decoder dot-products + loss partials
    k_decode<<<(NT + 7) / 8, 256>>>(tuser, titem, trating, W_dec, b_dec, out, NT);
    // 8. finalize loss
    k_final<<<1, 1>>>(out, NT, out_size > NT ? 1 : 0);
}

// round 2
// speedup vs baseline: 1.0059x; 1.0059x over previous
#include <cuda_runtime.h>
#include <cuda_bf16.h>
#include <math.h>
#include <stdint.h>

// ---- fixed problem shape (from reference) ----
#define NUM_ITEMS 50000
#define NUM_USERS 16384
#define H0 512
#define LAT 256
#define NMAX 262144

// ---- scratch (__device__ globals; no allocation allowed) ----
static __device__ float  g_WencT[(size_t)NUM_ITEMS * H0];   // [items, H0]
static __device__ float  g_x[(size_t)NUM_USERS * H0];
static __device__ float  g_enc[(size_t)NUM_USERS * LAT];
static __device__ float  g_dec[(size_t)NUM_USERS * H0];
static __device__ int    g_cnt[NUM_USERS];
static __device__ int    g_off[NUM_USERS + 1];
static __device__ int    g_cur[NUM_USERS];
static __device__ int    g_pitem[NMAX];
static __device__ float  g_prate[NMAX];
static __device__ double g_loss;

// ---------------- zero ----------------
__global__ void k_zero() {
    int i = blockIdx.x * blockDim.x + threadIdx.x;
    if (i < NUM_USERS) g_cnt[i] = 0;
    if (i == 0) g_loss = 0.0;
}

// ---------------- transpose W_enc [H0, NUM_ITEMS] -> g_WencT [NUM_ITEMS, H0] ----------------
__global__ void k_transpose(const float* __restrict__ W) {
    __shared__ float tile[32][33];
    int tx = threadIdx.x, ty = threadIdx.y;               // blockDim (32, 8)
    int col0 = blockIdx.x * 32;                           // item base
    int row0 = blockIdx.y * 32;                           // h base
    #pragma unroll
    for (int j = 0; j < 4; j++) {
        int r = ty + j * 8;
        int c = col0 + tx;
        if (c < NUM_ITEMS)
            tile[r][tx] = W[(size_t)(row0 + r) * NUM_ITEMS + c];
    }
    __syncthreads();
    #pragma unroll
    for (int j = 0; j < 4; j++) {
        int i = col0 + ty + j * 8;                         // item
        int h = row0 + tx;                                 // h
        if (i < NUM_ITEMS)
            g_WencT[(size_t)i * H0 + h] = tile[tx][ty + j * 8];
    }
}

// ---------------- histogram ----------------
__global__ void k_hist(const int* __restrict__ user, int n) {
    int i = blockIdx.x * blockDim.x + threadIdx.x;
    if (i < n) atomicAdd(&g_cnt[user[i]], 1);
}

// ---------------- exclusive scan over 16384 counts (one block, shuffle-based) ----------------
__global__ void k_scan() {
    int t = threadIdx.x;                                   // 1024 threads
    int lane = t & 31, wid = t >> 5;
    int base = t * 16;
    int local[16];
    int s = 0;
    #pragma unroll
    for (int i = 0; i < 16; i++) { local[i] = g_cnt[base + i]; s += local[i]; }
    // inclusive warp scan of s
    int v = s;
    #pragma unroll
    for (int o = 1; o < 32; o <<= 1) {
        int u = __shfl_up_sync(0xffffffffu, v, o);
        if (lane >= o) v += u;
    }
    __shared__ int wsum[32];
    if (lane == 31) wsum[wid] = v;
    __syncthreads();
    if (wid == 0) {
        int w = wsum[lane];
        #pragma unroll
        for (int o = 1; o < 32; o <<= 1) {
            int u = __shfl_up_sync(0xffffffffu, w, o);
            if (lane >= o) w += u;
        }
        wsum[lane] = w;
    }
    __syncthreads();
    int run = (wid ? wsum[wid - 1] : 0) + (v - s);         // exclusive prefix for this thread
    #pragma unroll
    for (int i = 0; i < 16; i++) {
        g_off[base + i] = run;
        g_cur[base + i] = run;
        run += local[i];
    }
    if (t == 1023) g_off[NUM_USERS] = run;
}

// ---------------- scatter (counting sort payloads) ----------------
__global__ void k_scatter(const int* __restrict__ user, const int* __restrict__ item,
                          const float* __restrict__ rating, int n) {
    int i = blockIdx.x * blockDim.x + threadIdx.x;
    if (i < n) {
        int p = atomicAdd(&g_cur[user[i]], 1);
        g_pitem[p] = item[i];
        g_prate[p] = rating[i];
    }
}

// ---------------- per-user encoder aggregation + tanh(+b_enc) ----------------
__global__ void k_encode(const float* __restrict__ b_enc) {
    int u = blockIdx.x;
    int t = threadIdx.x;                                   // 128 threads, float4 lanes
    int s = g_off[u], e = g_off[u + 1];
    const float4* WT4 = (const float4*)g_WencT;
    float4 acc = make_float4(0.f, 0.f, 0.f, 0.f);
    __shared__ int   sit[128];
    __shared__ float srt[128];
    for (int j0 = s; j0 < e; j0 += 128) {
        int c = min(128, e - j0);
        if (t < c) { sit[t] = g_pitem[j0 + t]; srt[t] = g_prate[j0 + t]; }
        __syncthreads();
        for (int q = 0; q < c; q++) {
            int it = sit[q]; float r = srt[q];
            float4 w = WT4[(size_t)it * 128 + t];
            acc.x = fmaf(r, w.x, acc.x);
            acc.y = fmaf(r, w.y, acc.y);
            acc.z = fmaf(r, w.z, acc.z);
            acc.w = fmaf(r, w.w, acc.w);
        }
        __syncthreads();
    }
    float4 b = ((const float4*)b_enc)[t];
    float4 xv;
    xv.x = tanhf(acc.x + b.x);
    xv.y = tanhf(acc.y + b.y);
    xv.z = tanhf(acc.z + b.z);
    xv.w = tanhf(acc.w + b.w);
    ((float4*)g_x)[(size_t)u * 128 + t] = xv;
}

// ---------------- TF32 tensor-core GEMM (3xTF32 split for fp32 accuracy) ----------------
// C[M,N] = tanh(A[M,K] @ B[N,K]^T + bias[N])
// Block tile 128x128, BK=16, 256 threads = 8 warps in 2(M) x 4(N), warp tile 64x32.

__device__ __forceinline__ uint32_t f2tf32(float x) {
    uint32_t r;
    asm("cvt.rna.tf32.f32 %0, %1;" : "=r"(r) : "f"(x));
    return r;
}

#define MMA_TF32(c, a0, a1, a2, a3, b0, b1)                                         \
    asm volatile("mma.sync.aligned.m16n8k8.row.col.f32.tf32.tf32.f32 "              \
                 "{%0,%1,%2,%3},{%4,%5,%6,%7},{%8,%9},{%0,%1,%2,%3};"               \
                 : "+f"(c[0]), "+f"(c[1]), "+f"(c[2]), "+f"(c[3])                   \
                 : "r"(a0), "r"(a1), "r"(a2), "r"(a3), "r"(b0), "r"(b1))

__global__ void __launch_bounds__(256, 1)
k_gemm_tf32(const float* __restrict__ A, const float* __restrict__ B,
            const float* __restrict__ bias, float* __restrict__ C,
            int M, int N, int K) {
    __shared__ float As[16][136];   // [k][m], pad 8 -> k-groups on disjoint bank octets
    __shared__ float Bs[16][136];   // [k][n]

    int tid = threadIdx.x;
    int lane = tid & 31;
    int wid = tid >> 5;
    int warp_m = wid & 1;           // 0..1
    int warp_n = wid >> 1;          // 0..3
    int gr = lane >> 2;             // 0..7
    int gc = lane & 3;              // 0..3

    int bm = blockIdx.y * 128;
    int bn = blockIdx.x * 128;

    int lr = tid >> 1;              // 0..127 : row within tile
    int lk = (tid & 1) * 8;         // 0 or 8 : k offset

    float acc[4][4][4];
    #pragma unroll
    for (int i = 0; i < 4; i++)
        #pragma unroll
        for (int j = 0; j < 4; j++)
            #pragma unroll
            for (int q = 0; q < 4; q++) acc[i][j][q] = 0.f;

    const int mb = warp_m * 64;
    const int nb = warp_n * 32;

    for (int k0 = 0; k0 < K; k0 += 16) {
        // global -> smem (transposed to [k][row])
        {
            const float4* Ag = (const float4*)(A + (size_t)(bm + lr) * K + k0 + lk);
            float4 a0 = Ag[0], a1 = Ag[1];
            As[lk + 0][lr] = a0.x; As[lk + 1][lr] = a0.y;
            As[lk + 2][lr] = a0.z; As[lk + 3][lr] = a0.w;
            As[lk + 4][lr] = a1.x; As[lk + 5][lr] = a1.y;
            As[lk + 6][lr] = a1.z; As[lk + 7][lr] = a1.w;
            const float4* Bg = (const float4*)(B + (size_t)(bn + lr) * K + k0 + lk);
            float4 b0 = Bg[0], b1 = Bg[1];
            Bs[lk + 0][lr] = b0.x; Bs[lk + 1][lr] = b0.y;
            Bs[lk + 2][lr] = b0.z; Bs[lk + 3][lr] = b0.w;
            Bs[lk + 4][lr] = b1.x; Bs[lk + 5][lr] = b1.y;
            Bs[lk + 6][lr] = b1.z; Bs[lk + 7][lr] = b1.w;
        }
        __syncthreads();

        #pragma unroll
        for (int ks = 0; ks < 16; ks += 8) {
            uint32_t Ah[4][4], Al[4][4], Bh[4][2], Bl[4][2];
            #pragma unroll
            for (int mt = 0; mt < 4; mt++) {
                int m0 = mb + mt * 16;
                float v0 = As[ks + gc][m0 + gr];
                float v1 = As[ks + gc][m0 + gr + 8];
                float v2 = As[ks + gc + 4][m0 + gr];
                float v3 = As[ks + gc + 4][m0 + gr + 8];
                Ah[mt][0] = f2tf32(v0); Al[mt][0] = f2tf32(v0 - __uint_as_float(Ah[mt][0]));
                Ah[mt][1] = f2tf32(v1); Al[mt][1] = f2tf32(v1 - __uint_as_float(Ah[mt][1]));
                Ah[mt][2] = f2tf32(v2); Al[mt][2] = f2tf32(v2 - __uint_as_float(Ah[mt][2]));
                Ah[mt][3] = f2tf32(v3); Al[mt][3] = f2tf32(v3 - __uint_as_float(Ah[mt][3]));
            }
            #pragma unroll
            for (int nt = 0; nt < 4; nt++) {
                int n0 = nb + nt * 8;
                float w0 = Bs[ks + gc][n0 + gr];
                float w1 = Bs[ks + gc + 4][n0 + gr];
                Bh[nt][0] = f2tf32(w0); Bl[nt][0] = f2tf32(w0 - __uint_as_float(Bh[nt][0]));
                Bh[nt][1] = f2tf32(w1); Bl[nt][1] = f2tf32(w1 - __uint_as_float(Bh[nt][1]));
            }
            #pragma unroll
            for (int mt = 0; mt < 4; mt++)
                #pragma unroll
                for (int nt = 0; nt < 4; nt++) {
                    MMA_TF32(acc[mt][nt], Ah[mt][0], Ah[mt][1], Ah[mt][2], Ah[mt][3],
                             Bh[nt][0], Bh[nt][1]);
                    MMA_TF32(acc[mt][nt], Ah[mt][0], Ah[mt][1], Ah[mt][2], Ah[mt][3],
                             Bl[nt][0], Bl[nt][1]);
                    MMA_TF32(acc[mt][nt], Al[mt][0], Al[mt][1], Al[mt][2], Al[mt][3],
                             Bh[nt][0], Bh[nt][1]);
                }
        }
        __syncthreads();
    }

    // epilogue: bias + tanh
    #pragma unroll
    for (int nt = 0; nt < 4; nt++) {
        int n0 = bn + nb + nt * 8 + gc * 2;
        float2 bv = *(const float2*)&bias[n0];
        #pragma unroll
        for (int mt = 0; mt < 4; mt++) {
            int m0 = bm + mb + mt * 16 + gr;
            float2 o0, o1;
            o0.x = tanhf(acc[mt][nt][0] + bv.x);
            o0.y = tanhf(acc[mt][nt][1] + bv.y);
            o1.x = tanhf(acc[mt][nt][2] + bv.x);
            o1.y = tanhf(acc[mt][nt][3] + bv.y);
            *(float2*)&C[(size_t)m0 * N + n0] = o0;
            *(float2*)&C[(size_t)(m0 + 8) * N + n0] = o1;
        }
    }
}

// ---------------- decoder: pred + MSE partials ----------------
__global__ void k_decode(const int* __restrict__ tuser, const int* __restrict__ titem,
                         const float* __restrict__ trating, const float* __restrict__ Wdec,
                         const float* __restrict__ bdec, float* __restrict__ out, int nt) {
    int warp = threadIdx.x >> 5, lane = threadIdx.x & 31;
    int t = blockIdx.x * 8 + warp;
    __shared__ double part[8];
    double mine = 0.0;
    if (t < nt) {
        int u = tuser[t], it = titem[t];
        const float4* g = (const float4*)g_dec + (size_t)u * 128;
        const float4* w = (const float4*)Wdec + (size_t)it * 128;
        float s = 0.f;
        #pragma unroll
        for (int q = 0; q < 4; q++) {
            float4 a = g[q * 32 + lane];
            float4 b = w[q * 32 + lane];
            s = fmaf(a.x, b.x, s);
            s = fmaf(a.y, b.y, s);
            s = fmaf(a.z, b.z, s);
            s = fmaf(a.w, b.w, s);
        }
        #pragma unroll
        for (int o = 16; o; o >>= 1) s += __shfl_xor_sync(0xffffffff, s, o);
        if (lane == 0) {
            float pred = s + bdec[it];
            out[t] = pred;
            float d = pred - trating[t];
            mine = (double)d * (double)d;
        }
    }
    if (lane == 0) part[warp] = mine;
    __syncthreads();
    if (threadIdx.x == 0) {
        double ss = 0.0;
        #pragma unroll
        for (int i = 0; i < 8; i++) ss += part[i];
        atomicAdd(&g_loss, ss);
    }
}

__global__ void k_final(float* out, int nt, int write_loss) {
    if (write_loss) out[nt] = (float)(g_loss / (double)nt);
}

// ---------------- launch ----------------
extern "C" void kernel_launch(void* const* d_in, const int* in_sizes, int n_in,
                              void* d_out, int out_size) {
    const int*   user    = (const int*)d_in[0];
    const int*   item    = (const int*)d_in[1];
    const float* rating  = (const float*)d_in[2];
    const int*   tuser   = (const int*)d_in[3];
    const int*   titem   = (const int*)d_in[4];
    const float* trating = (const float*)d_in[5];
    const float* W_enc   = (const float*)d_in[6];
    const float* b_enc   = (const float*)d_in[7];
    const float* W1      = (const float*)d_in[8];
    const float* b1      = (const float*)d_in[9];
    const float* W2      = (const float*)d_in[10];
    const float* b2      = (const float*)d_in[11];
    const float* W_dec   = (const float*)d_in[12];
    const float* b_dec   = (const float*)d_in[13];
    float* out = (float*)d_out;

    int N  = in_sizes[0];
    int NT = in_sizes[3];
    (void)n_in;

    // 1. zero counters + loss
    k_zero<<<(NUM_USERS + 255) / 256, 256>>>();
    // 2. transpose W_enc
    {
        dim3 b(32, 8), g((NUM_ITEMS + 31) / 32, H0 / 32);
        k_transpose<<<g, b>>>(W_enc);
    }
    // 3. counting sort by user
    k_hist<<<(N + 255) / 256, 256>>>(user, N);
    k_scan<<<1, 1024>>>();
    k_scatter<<<(N + 255) / 256, 256>>>(user, item, rating, N);
    // 4. per-user encoder aggregation + tanh
    k_encode<<<NUM_USERS, 128>>>(b_enc);
    // 5+6. MLP GEMMs on tensor cores (3xTF32)
    {
        float* enc_ptr; cudaGetSymbolAddress((void**)&enc_ptr, g_enc);
        float* x_ptr;   cudaGetSymbolAddress((void**)&x_ptr, g_x);
        float* dec_ptr; cudaGetSymbolAddress((void**)&dec_ptr, g_dec);
        dim3 g1(LAT / 128, NUM_USERS / 128);
        k_gemm_tf32<<<g1, 256>>>(x_ptr, W1, b1, enc_ptr, NUM_USERS, LAT, H0);
        dim3 g2(H0 / 128, NUM_USERS / 128);
        k_gemm_tf32<<<g2, 256>>>(enc_ptr, W2, b2, dec_ptr, NUM_USERS, H0, LAT);
    }
    // 7. decoder dot-products + loss partials
    k_decode<<<(NT + 7) / 8, 256>>>(tuser, titem, trating, W_dec, b_dec, out, NT);
    // 8. finalize loss
    k_final<<<1, 1>>>(out, NT, out_size > NT ? 1 : 0);
}

// round 4
// speedup vs baseline: 1.3012x; 1.2936x over previous
#include <cuda_runtime.h>
#include <cuda_bf16.h>
#include <math.h>
#include <stdint.h>

// ---- fixed problem shape ----
#define NUM_ITEMS 50000
#define NUM_USERS 16384
#define H0 512
#define LAT 256
#define NMAX 262144

// ---- scratch ----
static __device__ float  g_WencT[(size_t)NUM_ITEMS * H0];
static __device__ float  g_x[(size_t)NUM_USERS * H0];
static __device__ float  g_enc[(size_t)NUM_USERS * LAT];
static __device__ float  g_dec[(size_t)NUM_USERS * H0];
static __device__ int    g_cnt[NUM_USERS];
static __device__ int    g_off[NUM_USERS + 1];
static __device__ int    g_cur[NUM_USERS];
static __device__ int    g_blksum[64];
static __device__ int    g_blkoff[64];
static __device__ int    g_pitem[NMAX];
static __device__ float  g_prate[NMAX];
static __device__ double g_loss;

// ================= small kernels =================
__global__ void k_transpose(const float* __restrict__ W) {
    __shared__ float tile[32][33];
    int tx = threadIdx.x, ty = threadIdx.y;
    int col0 = blockIdx.x * 32;
    int row0 = blockIdx.y * 32;
    #pragma unroll
    for (int j = 0; j < 4; j++) {
        int r = ty + j * 8, c = col0 + tx;
        if (c < NUM_ITEMS) tile[r][tx] = W[(size_t)(row0 + r) * NUM_ITEMS + c];
    }
    __syncthreads();
    #pragma unroll
    for (int j = 0; j < 4; j++) {
        int i = col0 + ty + j * 8, h = row0 + tx;
        if (i < NUM_ITEMS) g_WencT[(size_t)i * H0 + h] = tile[tx][ty + j * 8];
    }
}

__global__ void k_hist(const int* __restrict__ user, int n) {
    int i = blockIdx.x * blockDim.x + threadIdx.x;
    if (i < n) atomicAdd(&g_cnt[user[i]], 1);
}

__global__ void k_scan1() {
    int b = blockIdx.x, t = threadIdx.x;                   // 64 blocks x 256
    int u = (b << 8) + t;
    int v = g_cnt[u];
    int lane = t & 31, w = t >> 5;
    int s = v;
    #pragma unroll
    for (int o = 1; o < 32; o <<= 1) {
        int x = __shfl_up_sync(0xffffffffu, s, o);
        if (lane >= o) s += x;
    }
    __shared__ int ws[8];
    if (lane == 31) ws[w] = s;
    __syncthreads();
    int add = 0;
    #pragma unroll
    for (int q = 0; q < 8; q++) if (q < w) add += ws[q];
    g_off[u] = add + s - v;
    if (t == 255) g_blksum[b] = add + s;
}

__global__ void k_scan2(int n) {
    int t = threadIdx.x;                                   // 64 threads
    int v = g_blksum[t];
    int lane = t & 31, w = t >> 5;
    int s = v;
    #pragma unroll
    for (int o = 1; o < 32; o <<= 1) {
        int x = __shfl_up_sync(0xffffffffu, s, o);
        if (lane >= o) s += x;
    }
    __shared__ int ws[2];
    if (lane == 31) ws[w] = s;
    __syncthreads();
    g_blkoff[t] = s - v + (w ? ws[0] : 0);
    if (t == 63) g_off[NUM_USERS] = n;
}

__global__ void k_scan3() {
    int u = blockIdx.x * 256 + threadIdx.x;
    int o = g_off[u] + g_blkoff[blockIdx.x];
    g_off[u] = o;
    g_cur[u] = o;
}

__global__ void k_scatter(const int* __restrict__ user, const int* __restrict__ item,
                          const float* __restrict__ rating, int n) {
    int i = blockIdx.x * blockDim.x + threadIdx.x;
    if (i < n) {
        int p = atomicAdd(&g_cur[user[i]], 1);
        g_pitem[p] = item[i];
        g_prate[p] = rating[i];
    }
}

__global__ void k_encode(const float* __restrict__ b_enc) {
    int u = blockIdx.x;
    int t = threadIdx.x;                                   // 128
    int s = g_off[u], e = g_off[u + 1];
    const float4* WT4 = (const float4*)g_WencT;
    float4 acc0 = make_float4(0.f, 0.f, 0.f, 0.f);
    float4 acc1 = make_float4(0.f, 0.f, 0.f, 0.f);
    __shared__ int   sit[128];
    __shared__ float srt[128];
    for (int j0 = s; j0 < e; j0 += 128) {
        int c = min(128, e - j0);
        if (t < c) { sit[t] = g_pitem[j0 + t]; srt[t] = g_prate[j0 + t]; }
        __syncthreads();
        int q = 0;
        for (; q + 1 < c; q += 2) {
            int i0 = sit[q], i1 = sit[q + 1];
            float r0 = srt[q], r1 = srt[q + 1];
            float4 w0 = WT4[(size_t)i0 * 128 + t];
            float4 w1 = WT4[(size_t)i1 * 128 + t];
            acc0.x = fmaf(r0, w0.x, acc0.x); acc1.x = fmaf(r1, w1.x, acc1.x);
            acc0.y = fmaf(r0, w0.y, acc0.y); acc1.y = fmaf(r1, w1.y, acc1.y);
            acc0.z = fmaf(r0, w0.z, acc0.z); acc1.z = fmaf(r1, w1.z, acc1.z);
            acc0.w = fmaf(r0, w0.w, acc0.w); acc1.w = fmaf(r1, w1.w, acc1.w);
        }
        if (q < c) {
            int i0 = sit[q]; float r0 = srt[q];
            float4 w0 = WT4[(size_t)i0 * 128 + t];
            acc0.x = fmaf(r0, w0.x, acc0.x);
            acc0.y = fmaf(r0, w0.y, acc0.y);
            acc0.z = fmaf(r0, w0.z, acc0.z);
            acc0.w = fmaf(r0, w0.w, acc0.w);
        }
        __syncthreads();
    }
    float4 b = ((const float4*)b_enc)[t];
    float4 xv;
    xv.x = tanhf(acc0.x + acc1.x + b.x);
    xv.y = tanhf(acc0.y + acc1.y + b.y);
    xv.z = tanhf(acc0.z + acc1.z + b.z);
    xv.w = tanhf(acc0.w + acc1.w + b.w);
    ((float4*)g_x)[(size_t)u * 128 + t] = xv;
}

// ================= bf16 3-way-split tensor-core GEMM =================
// C[M,N] = tanh(A[M,K] @ B[N,K]^T + bias[N])
// Block tile 128x128, BK=32, 256 threads = 8 warps (2M x 4N), warp tile 64x32.
// Product split: A = Ah + Al, B = Bh + Bl (bf16); C ~= Ah*Bh + Ah*Bl + Al*Bh.
// hi/lo split done ONCE at tile load into smem; inner loop = LDS + MMA only.

__device__ __forceinline__ uint32_t packbf(float x, float y) {
    __nv_bfloat162 v = __floats2bfloat162_rn(x, y);
    return *(uint32_t*)&v;
}

#define MMA_BF16(c, a0, a1, a2, a3, b0, b1)                                         \
    asm volatile("mma.sync.aligned.m16n8k16.row.col.f32.bf16.bf16.f32 "             \
                 "{%0,%1,%2,%3},{%4,%5,%6,%7},{%8,%9},{%0,%1,%2,%3};"               \
                 : "+f"(c[0]), "+f"(c[1]), "+f"(c[2]), "+f"(c[3])                   \
                 : "r"(a0), "r"(a1), "r"(a2), "r"(a3), "r"(b0), "r"(b1))

#define SPITCH 136

__global__ void __launch_bounds__(256, 1)
k_gemm_bf16x3(const float* __restrict__ A, const float* __restrict__ B,
              const float* __restrict__ bias, float* __restrict__ C,
              int M, int N, int K) {
    __shared__ uint32_t sAh[16][SPITCH], sAl[16][SPITCH];
    __shared__ uint32_t sBh[16][SPITCH], sBl[16][SPITCH];
    __shared__ float bias_s[128];

    int tid = threadIdx.x;
    int lane = tid & 31;
    int wid = tid >> 5;
    int warp_m = wid & 1;
    int warp_n = wid >> 1;
    int gr = lane >> 2;             // 0..7
    int gc = lane & 3;              // 0..3

    int bm = blockIdx.y * 128;
    int bn = blockIdx.x * 128;

    if (tid < 128) bias_s[tid] = bias[bn + tid];

    float acc[4][4][4];
    #pragma unroll
    for (int i = 0; i < 4; i++)
        #pragma unroll
        for (int j = 0; j < 4; j++)
            #pragma unroll
            for (int q = 0; q < 4; q++) acc[i][j][q] = 0.f;

    const int mb = warp_m * 64;
    const int nb = warp_n * 32;
    const int r  = tid >> 1;        // 0..127 (row within tile) for loads
    const int c8 = (tid & 1) * 4;   // float4-group: covers k offsets c8*4..c8*4+15

    for (int k0 = 0; k0 < K; k0 += 32) {
        // ---- load 128x32 A and B slabs, split hi/lo, store bf16x2 [k2][row] ----
        #pragma unroll
        for (int g = 0; g < 4; g++) {
            int c4 = c8 + g;                         // 0..7, k = k0 + c4*4
            float4 a = *(const float4*)(A + (size_t)(bm + r) * K + k0 + c4 * 4);
            float hx = __bfloat162float(__float2bfloat16_rn(a.x));
            float hy = __bfloat162float(__float2bfloat16_rn(a.y));
            float hz = __bfloat162float(__float2bfloat16_rn(a.z));
            float hw = __bfloat162float(__float2bfloat16_rn(a.w));
            sAh[c4 * 2 + 0][r] = packbf(hx, hy);
            sAh[c4 * 2 + 1][r] = packbf(hz, hw);
            sAl[c4 * 2 + 0][r] = packbf(a.x - hx, a.y - hy);
            sAl[c4 * 2 + 1][r] = packbf(a.z - hz, a.w - hw);
            float4 b = *(const float4*)(B + (size_t)(bn + r) * K + k0 + c4 * 4);
            hx = __bfloat162float(__float2bfloat16_rn(b.x));
            hy = __bfloat162float(__float2bfloat16_rn(b.y));
            hz = __bfloat162float(__float2bfloat16_rn(b.z));
            hw = __bfloat162float(__float2bfloat16_rn(b.w));
            sBh[c4 * 2 + 0][r] = packbf(hx, hy);
            sBh[c4 * 2 + 1][r] = packbf(hz, hw);
            sBl[c4 * 2 + 0][r] = packbf(b.x - hx, b.y - hy);
            sBl[c4 * 2 + 1][r] = packbf(b.z - hz, b.w - hw);
        }
        __syncthreads();

        // ---- compute: 2 k16 steps ----
        #pragma unroll
        for (int ks = 0; ks < 2; ks++) {
            int kb = ks * 8;
            uint32_t Ah[4][4], Al[4][4], Bh[4][2], Bl[4][2];
            #pragma unroll
            for (int mt = 0; mt < 4; mt++) {
                int m0 = mb + mt * 16 + gr;
                Ah[mt][0] = sAh[kb + gc][m0];
                Ah[mt][1] = sAh[kb + gc][m0 + 8];
                Ah[mt][2] = sAh[kb + gc + 4][m0];
                Ah[mt][3] = sAh[kb + gc + 4][m0 + 8];
                Al[mt][0] = sAl[kb + gc][m0];
                Al[mt][1] = sAl[kb + gc][m0 + 8];
                Al[mt][2] = sAl[kb + gc + 4][m0];
                Al[mt][3] = sAl[kb + gc + 4][m0 + 8];
            }
            #pragma unroll
            for (int nt = 0; nt < 4; nt++) {
                int n0 = nb + nt * 8 + gr;
                Bh[nt][0] = sBh[kb + gc][n0];
                Bh[nt][1] = sBh[kb + gc + 4][n0];
                Bl[nt][0] = sBl[kb + gc][n0];
                Bl[nt][1] = sBl[kb + gc + 4][n0];
            }
            #pragma unroll
            for (int mt = 0; mt < 4; mt++)
                #pragma unroll
                for (int nt = 0; nt < 4; nt++) {
                    MMA_BF16(acc[mt][nt], Ah[mt][0], Ah[mt][1], Ah[mt][2], Ah[mt][3],
                             Bh[nt][0], Bh[nt][1]);
                    MMA_BF16(acc[mt][nt], Ah[mt][0], Ah[mt][1], Ah[mt][2], Ah[mt][3],
                             Bl[nt][0], Bl[nt][1]);
                    MMA_BF16(acc[mt][nt], Al[mt][0], Al[mt][1], Al[mt][2], Al[mt][3],
                             Bh[nt][0], Bh[nt][1]);
                }
        }
        __syncthreads();
    }

    // ---- epilogue: bias + tanh ----
    #pragma unroll
    for (int nt = 0; nt < 4; nt++) {
        int nc = nb + nt * 8 + gc * 2;
        float2 bv = make_float2(bias_s[nc], bias_s[nc + 1]);
        int n0 = bn + nc;
        #pragma unroll
        for (int mt = 0; mt < 4; mt++) {
            int m0 = bm + mb + mt * 16 + gr;
            float2 o0, o1;
            o0.x = tanhf(acc[mt][nt][0] + bv.x);
            o0.y = tanhf(acc[mt][nt][1] + bv.y);
            o1.x = tanhf(acc[mt][nt][2] + bv.x);
            o1.y = tanhf(acc[mt][nt][3] + bv.y);
            *(float2*)&C[(size_t)m0 * N + n0] = o0;
            *(float2*)&C[(size_t)(m0 + 8) * N + n0] = o1;
        }
    }
}

// ================= decoder =================
__global__ void k_decode(const int* __restrict__ tuser, const int* __restrict__ titem,
                         const float* __restrict__ trating, const float* __restrict__ Wdec,
                         const float* __restrict__ bdec, float* __restrict__ out, int nt) {
    int warp = threadIdx.x >> 5, lane = threadIdx.x & 31;
    int t = blockIdx.x * 8 + warp;
    __shared__ double part[8];
    double mine = 0.0;
    if (t < nt) {
        int u = tuser[t], it = titem[t];
        const float4* g = (const float4*)g_dec + (size_t)u * 128;
        const float4* w = (const float4*)Wdec + (size_t)it * 128;
        float s = 0.f;
        #pragma unroll
        for (int q = 0; q < 4; q++) {
            float4 a = g[q * 32 + lane];
            float4 b = w[q * 32 + lane];
            s = fmaf(a.x, b.x, s);
            s = fmaf(a.y, b.y, s);
            s = fmaf(a.z, b.z, s);
            s = fmaf(a.w, b.w, s);
        }
        #pragma unroll
        for (int o = 16; o; o >>= 1) s += __shfl_xor_sync(0xffffffff, s, o);
        if (lane == 0) {
            float pred = s + bdec[it];
            out[t] = pred;
            float d = pred - trating[t];
            mine = (double)d * (double)d;
        }
    }
    if (lane == 0) part[warp] = mine;
    __syncthreads();
    if (threadIdx.x == 0) {
        double ss = 0.0;
        #pragma unroll
        for (int i = 0; i < 8; i++) ss += part[i];
        atomicAdd(&g_loss, ss);
    }
}

__global__ void k_final(float* out, int nt, int write_loss) {
    if (write_loss) out[nt] = (float)(g_loss / (double)nt);
}

// ================= launch =================
extern "C" void kernel_launch(void* const* d_in, const int* in_sizes, int n_in,
                              void* d_out, int out_size) {
    const int*   user    = (const int*)d_in[0];
    const int*   item    = (const int*)d_in[1];
    const float* rating  = (const float*)d_in[2];
    const int*   tuser   = (const int*)d_in[3];
    const int*   titem   = (const int*)d_in[4];
    const float* trating = (const float*)d_in[5];
    const float* W_enc   = (const float*)d_in[6];
    const float* b_enc   = (const float*)d_in[7];
    const float* W1      = (const float*)d_in[8];
    const float* b1      = (const float*)d_in[9];
    const float* W2      = (const float*)d_in[10];
    const float* b2      = (const float*)d_in[11];
    const float* W_dec   = (const float*)d_in[12];
    const float* b_dec   = (const float*)d_in[13];
    float* out = (float*)d_out;

    int N  = in_sizes[0];
    int NT = in_sizes[3];
    (void)n_in;

    void *cnt_ptr, *loss_ptr, *x_ptr, *enc_ptr, *dec_ptr;
    cudaGetSymbolAddress(&cnt_ptr, g_cnt);
    cudaGetSymbolAddress(&loss_ptr, g_loss);
    cudaGetSymbolAddress(&x_ptr, g_x);
    cudaGetSymbolAddress(&enc_ptr, g_enc);
    cudaGetSymbolAddress(&dec_ptr, g_dec);

    // zero counters + loss
    cudaMemsetAsync(cnt_ptr, 0, NUM_USERS * sizeof(int), 0);
    cudaMemsetAsync(loss_ptr, 0, sizeof(double), 0);
    // transpose W_enc
    {
        dim3 b(32, 8), g((NUM_ITEMS + 31) / 32, H0 / 32);
        k_transpose<<<g, b>>>(W_enc);
    }
    // counting sort by user
    k_hist<<<(N + 255) / 256, 256>>>(user, N);
    k_scan1<<<64, 256>>>();
    k_scan2<<<1, 64>>>(N);
    k_scan3<<<64, 256>>>();
    k_scatter<<<(N + 255) / 256, 256>>>(user, item, rating, N);
    // encoder aggregation + tanh
    k_encode<<<NUM_USERS, 128>>>(b_enc);
    // MLP GEMMs (bf16 3-way split on tensor cores)
    {
        dim3 g1(LAT / 128, NUM_USERS / 128);
        k_gemm_bf16x3<<<g1, 256>>>((const float*)x_ptr, W1, b1, (float*)enc_ptr,
                                   NUM_USERS, LAT, H0);
        dim3 g2(H0 / 128, NUM_USERS / 128);
        k_gemm_bf16x3<<<g2, 256>>>((const float*)enc_ptr, W2, b2, (float*)dec_ptr,
                                   NUM_USERS, H0, LAT);
    }
    // decoder + loss
    k_decode<<<(NT + 7) / 8, 256>>>(tuser, titem, trating, W_dec, b_dec, out, NT);
    k_final<<<1, 1>>>(out, NT, out_size > NT ? 1 : 0);
}

// round 5
// speedup vs baseline: 1.3107x; 1.0072x over previous
#include <cuda_runtime.h>
#include <cuda_bf16.h>
#include <math.h>
#include <stdint.h>

// ---- fixed problem shape ----
#define NUM_ITEMS 50000
#define NUM_USERS 16384
#define H0 512
#define LAT 256
#define NMAX 262144

// ---- scratch ----
static __device__ float  g_WencT[(size_t)NUM_ITEMS * H0];
static __device__ __nv_bfloat16 g_xh[(size_t)NUM_USERS * H0];
static __device__ __nv_bfloat16 g_xl[(size_t)NUM_USERS * H0];
static __device__ __nv_bfloat16 g_ench[(size_t)NUM_USERS * LAT];
static __device__ __nv_bfloat16 g_encl[(size_t)NUM_USERS * LAT];
static __device__ __nv_bfloat16 g_w1h[(size_t)LAT * H0];
static __device__ __nv_bfloat16 g_w1l[(size_t)LAT * H0];
static __device__ __nv_bfloat16 g_w2h[(size_t)H0 * LAT];
static __device__ __nv_bfloat16 g_w2l[(size_t)H0 * LAT];
static __device__ float  g_dec[(size_t)NUM_USERS * H0];
static __device__ int    g_cnt[NUM_USERS];
static __device__ int    g_off[NUM_USERS + 1];
static __device__ int    g_cur[NUM_USERS];
static __device__ int    g_blksum[64];
static __device__ int    g_blkoff[64];
static __device__ int    g_pitem[NMAX];
static __device__ float  g_prate[NMAX];
static __device__ double g_loss;
static __device__ int    g_dcount;

// ================= small kernels =================
__global__ void k_transpose(const float* __restrict__ W) {
    __shared__ float tile[32][33];
    int tx = threadIdx.x, ty = threadIdx.y;
    int col0 = blockIdx.x * 32;
    int row0 = blockIdx.y * 32;
    #pragma unroll
    for (int j = 0; j < 4; j++) {
        int r = ty + j * 8, c = col0 + tx;
        if (c < NUM_ITEMS) tile[r][tx] = W[(size_t)(row0 + r) * NUM_ITEMS + c];
    }
    __syncthreads();
    #pragma unroll
    for (int j = 0; j < 4; j++) {
        int i = col0 + ty + j * 8, h = row0 + tx;
        if (i < NUM_ITEMS) g_WencT[(size_t)i * H0 + h] = tile[tx][ty + j * 8];
    }
}

// split W1 and W2 into bf16 hi/lo (one launch)
__global__ void k_convw(const float* __restrict__ W1, const float* __restrict__ W2) {
    int i = blockIdx.x * blockDim.x + threadIdx.x;            // 0 .. 2*131072/4-1 (float4 units)
    const int n1 = LAT * H0 / 4;                              // 32768 float4
    const float* src; __nv_bfloat16 *dh, *dl; int j;
    if (i < n1) { src = W1; dh = g_w1h; dl = g_w1l; j = i; }
    else        { src = W2; dh = g_w2h; dl = g_w2l; j = i - n1; }
    float4 v = ((const float4*)src)[j];
    __nv_bfloat16 hx = __float2bfloat16_rn(v.x);
    __nv_bfloat16 hy = __float2bfloat16_rn(v.y);
    __nv_bfloat16 hz = __float2bfloat16_rn(v.z);
    __nv_bfloat16 hw = __float2bfloat16_rn(v.w);
    ((__nv_bfloat162*)dh)[j * 2 + 0] = __nv_bfloat162(hx, hy);
    ((__nv_bfloat162*)dh)[j * 2 + 1] = __nv_bfloat162(hz, hw);
    ((__nv_bfloat162*)dl)[j * 2 + 0] = __nv_bfloat162(
        __float2bfloat16_rn(v.x - __bfloat162float(hx)),
        __float2bfloat16_rn(v.y - __bfloat162float(hy)));
    ((__nv_bfloat162*)dl)[j * 2 + 1] = __nv_bfloat162(
        __float2bfloat16_rn(v.z - __bfloat162float(hz)),
        __float2bfloat16_rn(v.w - __bfloat162float(hw)));
}

__global__ void k_hist(const int* __restrict__ user, int n) {
    int i = blockIdx.x * blockDim.x + threadIdx.x;
    if (i < n) atomicAdd(&g_cnt[user[i]], 1);
}

__global__ void k_scan1() {
    int b = blockIdx.x, t = threadIdx.x;                   // 64 blocks x 256
    int u = (b << 8) + t;
    int v = g_cnt[u];
    int lane = t & 31, w = t >> 5;
    int s = v;
    #pragma unroll
    for (int o = 1; o < 32; o <<= 1) {
        int x = __shfl_up_sync(0xffffffffu, s, o);
        if (lane >= o) s += x;
    }
    __shared__ int ws[8];
    if (lane == 31) ws[w] = s;
    __syncthreads();
    int add = 0;
    #pragma unroll
    for (int q = 0; q < 8; q++) if (q < w) add += ws[q];
    g_off[u] = add + s - v;
    if (t == 255) g_blksum[b] = add + s;
}

__global__ void k_scan2(int n) {
    int t = threadIdx.x;                                   // 64 threads
    int v = g_blksum[t];
    int lane = t & 31, w = t >> 5;
    int s = v;
    #pragma unroll
    for (int o = 1; o < 32; o <<= 1) {
        int x = __shfl_up_sync(0xffffffffu, s, o);
        if (lane >= o) s += x;
    }
    __shared__ int ws[2];
    if (lane == 31) ws[w] = s;
    __syncthreads();
    g_blkoff[t] = s - v + (w ? ws[0] : 0);
    if (t == 63) g_off[NUM_USERS] = n;
}

__global__ void k_scan3() {
    int u = blockIdx.x * 256 + threadIdx.x;
    int o = g_off[u] + g_blkoff[blockIdx.x];
    g_off[u] = o;
    g_cur[u] = o;
}

__global__ void k_scatter(const int* __restrict__ user, const int* __restrict__ item,
                          const float* __restrict__ rating, int n) {
    int i = blockIdx.x * blockDim.x + threadIdx.x;
    if (i < n) {
        int p = atomicAdd(&g_cur[user[i]], 1);
        g_pitem[p] = item[i];
        g_prate[p] = rating[i];
    }
}

// encoder aggregation + tanh, emits bf16 hi/lo of x
__global__ void k_encode(const float* __restrict__ b_enc) {
    int u = blockIdx.x;
    int t = threadIdx.x;                                   // 128
    int s = g_off[u], e = g_off[u + 1];
    const float4* WT4 = (const float4*)g_WencT;
    float4 acc0 = make_float4(0.f, 0.f, 0.f, 0.f);
    float4 acc1 = make_float4(0.f, 0.f, 0.f, 0.f);
    __shared__ int   sit[128];
    __shared__ float srt[128];
    for (int j0 = s; j0 < e; j0 += 128) {
        int c = min(128, e - j0);
        if (t < c) { sit[t] = g_pitem[j0 + t]; srt[t] = g_prate[j0 + t]; }
        __syncthreads();
        int q = 0;
        for (; q + 1 < c; q += 2) {
            int i0 = sit[q], i1 = sit[q + 1];
            float r0 = srt[q], r1 = srt[q + 1];
            float4 w0 = WT4[(size_t)i0 * 128 + t];
            float4 w1 = WT4[(size_t)i1 * 128 + t];
            acc0.x = fmaf(r0, w0.x, acc0.x); acc1.x = fmaf(r1, w1.x, acc1.x);
            acc0.y = fmaf(r0, w0.y, acc0.y); acc1.y = fmaf(r1, w1.y, acc1.y);
            acc0.z = fmaf(r0, w0.z, acc0.z); acc1.z = fmaf(r1, w1.z, acc1.z);
            acc0.w = fmaf(r0, w0.w, acc0.w); acc1.w = fmaf(r1, w1.w, acc1.w);
        }
        if (q < c) {
            int i0 = sit[q]; float r0 = srt[q];
            float4 w0 = WT4[(size_t)i0 * 128 + t];
            acc0.x = fmaf(r0, w0.x, acc0.x);
            acc0.y = fmaf(r0, w0.y, acc0.y);
            acc0.z = fmaf(r0, w0.z, acc0.z);
            acc0.w = fmaf(r0, w0.w, acc0.w);
        }
        __syncthreads();
    }
    float4 b = ((const float4*)b_enc)[t];
    float vx = tanhf(acc0.x + acc1.x + b.x);
    float vy = tanhf(acc0.y + acc1.y + b.y);
    float vz = tanhf(acc0.z + acc1.z + b.z);
    float vw = tanhf(acc0.w + acc1.w + b.w);
    __nv_bfloat16 hx = __float2bfloat16_rn(vx);
    __nv_bfloat16 hy = __float2bfloat16_rn(vy);
    __nv_bfloat16 hz = __float2bfloat16_rn(vz);
    __nv_bfloat16 hw = __float2bfloat16_rn(vw);
    size_t o2 = (size_t)u * 256 + t * 2;
    ((__nv_bfloat162*)g_xh)[o2 + 0] = __nv_bfloat162(hx, hy);
    ((__nv_bfloat162*)g_xh)[o2 + 1] = __nv_bfloat162(hz, hw);
    ((__nv_bfloat162*)g_xl)[o2 + 0] = __nv_bfloat162(
        __float2bfloat16_rn(vx - __bfloat162float(hx)),
        __float2bfloat16_rn(vy - __bfloat162float(hy)));
    ((__nv_bfloat162*)g_xl)[o2 + 1] = __nv_bfloat162(
        __float2bfloat16_rn(vz - __bfloat162float(hz)),
        __float2bfloat16_rn(vw - __bfloat162float(hw)));
}

// ================= bf16 3-way-split GEMM, pre-split inputs, pipelined =================
// C[M,N] = tanh(A[M,K] @ B[N,K]^T + bias[N]); A,B given as bf16 hi/lo.
// OUT_SPLIT=1: also emit bf16 hi/lo (Ch/Cl); OUT_SPLIT=0: emit fp32 C.

#define MMA_BF16(c, a0, a1, a2, a3, b0, b1)                                         \
    asm volatile("mma.sync.aligned.m16n8k16.row.col.f32.bf16.bf16.f32 "             \
                 "{%0,%1,%2,%3},{%4,%5,%6,%7},{%8,%9},{%0,%1,%2,%3};"               \
                 : "+f"(c[0]), "+f"(c[1]), "+f"(c[2]), "+f"(c[3])                   \
                 : "r"(a0), "r"(a1), "r"(a2), "r"(a3), "r"(b0), "r"(b1))

#define SPITCH 136
#define ARRU32 (16 * SPITCH)        // one [k2][row] slab
#define BUFU32 (4 * ARRU32)         // Ah, Al, Bh, Bl
#define GEMM_SMEM ((2 * BUFU32 + 128) * 4)

template <int OUT_SPLIT>
__global__ void __launch_bounds__(256, 1)
k_gemm(const __nv_bfloat16* __restrict__ Ah_g, const __nv_bfloat16* __restrict__ Al_g,
       const __nv_bfloat16* __restrict__ Bh_g, const __nv_bfloat16* __restrict__ Bl_g,
       const float* __restrict__ bias, float* __restrict__ C,
       __nv_bfloat16* __restrict__ Ch, __nv_bfloat16* __restrict__ Cl,
       int M, int N, int K) {
    extern __shared__ uint32_t sm[];
    float* bias_s = (float*)(sm + 2 * BUFU32);

    int tid = threadIdx.x;
    int lane = tid & 31;
    int wid = tid >> 5;
    int warp_m = wid & 1;
    int warp_n = wid >> 1;
    int gr = lane >> 2;
    int gc = lane & 3;

    int bm = blockIdx.y * 128;
    int bn = blockIdx.x * 128;

    if (tid < 128) bias_s[tid] = bias[bn + tid];

    float acc[4][4][4];
    #pragma unroll
    for (int i = 0; i < 4; i++)
        #pragma unroll
        for (int j = 0; j < 4; j++)
            #pragma unroll
            for (int q = 0; q < 4; q++) acc[i][j][q] = 0.f;

    const int mb = warp_m * 64;
    const int nb = warp_n * 32;
    const int r    = tid >> 1;       // row within tile
    const int half = tid & 1;        // which 16-wide k half of the 32 chunk
    const int kb2  = half * 8;       // k2 base for STS

    const __nv_bfloat16* pAh = Ah_g + (size_t)(bm + r) * K + half * 16;
    const __nv_bfloat16* pAl = Al_g + (size_t)(bm + r) * K + half * 16;
    const __nv_bfloat16* pBh = Bh_g + (size_t)(bn + r) * K + half * 16;
    const __nv_bfloat16* pBl = Bl_g + (size_t)(bn + r) * K + half * 16;

    uint4 rAh0, rAh1, rAl0, rAl1, rBh0, rBh1, rBl0, rBl1;

#define LDG_CHUNK(k0)                                                   \
    do {                                                                \
        rAh0 = *(const uint4*)(pAh + (k0));                             \
        rAh1 = *(const uint4*)(pAh + (k0) + 8);                         \
        rAl0 = *(const uint4*)(pAl + (k0));                             \
        rAl1 = *(const uint4*)(pAl + (k0) + 8);                         \
        rBh0 = *(const uint4*)(pBh + (k0));                             \
        rBh1 = *(const uint4*)(pBh + (k0) + 8);                         \
        rBl0 = *(const uint4*)(pBl + (k0));                             \
        rBl1 = *(const uint4*)(pBl + (k0) + 8);                         \
    } while (0)

#define STS_CHUNK(buf)                                                  \
    do {                                                                \
        uint32_t* b0 = sm + (buf) * BUFU32;                             \
        uint32_t* b1 = b0 + ARRU32;                                     \
        uint32_t* b2 = b0 + 2 * ARRU32;                                 \
        uint32_t* b3 = b0 + 3 * ARRU32;                                 \
        b0[(kb2 + 0) * SPITCH + r] = rAh0.x;                            \
        b0[(kb2 + 1) * SPITCH + r] = rAh0.y;                            \
        b0[(kb2 + 2) * SPITCH + r] = rAh0.z;                            \
        b0[(kb2 + 3) * SPITCH + r] = rAh0.w;                            \
        b0[(kb2 + 4) * SPITCH + r] = rAh1.x;                            \
        b0[(kb2 + 5) * SPITCH + r] = rAh1.y;                            \
        b0[(kb2 + 6) * SPITCH + r] = rAh1.z;                            \
        b0[(kb2 + 7) * SPITCH + r] = rAh1.w;                            \
        b1[(kb2 + 0) * SPITCH + r] = rAl0.x;                            \
        b1[(kb2 + 1) * SPITCH + r] = rAl0.y;                            \
        b1[(kb2 + 2) * SPITCH + r] = rAl0.z;                            \
        b1[(kb2 + 3) * SPITCH + r] = rAl0.w;                            \
        b1[(kb2 + 4) * SPITCH + r] = rAl1.x;                            \
        b1[(kb2 + 5) * SPITCH + r] = rAl1.y;                            \
        b1[(kb2 + 6) * SPITCH + r] = rAl1.z;                            \
        b1[(kb2 + 7) * SPITCH + r] = rAl1.w;                            \
        b2[(kb2 + 0) * SPITCH + r] = rBh0.x;                            \
        b2[(kb2 + 1) * SPITCH + r] = rBh0.y;                            \
        b2[(kb2 + 2) * SPITCH + r] = rBh0.z;                            \
        b2[(kb2 + 3) * SPITCH + r] = rBh0.w;                            \
        b2[(kb2 + 4) * SPITCH + r] = rBh1.x;                            \
        b2[(kb2 + 5) * SPITCH + r] = rBh1.y;                            \
        b2[(kb2 + 6) * SPITCH + r] = rBh1.z;                            \
        b2[(kb2 + 7) * SPITCH + r] = rBh1.w;                            \
        b3[(kb2 + 0) * SPITCH + r] = rBl0.x;                            \
        b3[(kb2 + 1) * SPITCH + r] = rBl0.y;                            \
        b3[(kb2 + 2) * SPITCH + r] = rBl0.z;                            \
        b3[(kb2 + 3) * SPITCH + r] = rBl0.w;                            \
        b3[(kb2 + 4) * SPITCH + r] = rBl1.x;                            \
        b3[(kb2 + 5) * SPITCH + r] = rBl1.y;                            \
        b3[(kb2 + 6) * SPITCH + r] = rBl1.z;                            \
        b3[(kb2 + 7) * SPITCH + r] = rBl1.w;                            \
    } while (0)

    const int NC = K / 32;
    LDG_CHUNK(0);
    STS_CHUNK(0);
    __syncthreads();

    for (int c = 0; c < NC; c++) {
        if (c + 1 < NC) LDG_CHUNK((c + 1) * 32);

        const uint32_t* bA_h = sm + (c & 1) * BUFU32;
        const uint32_t* bA_l = bA_h + ARRU32;
        const uint32_t* bB_h = bA_h + 2 * ARRU32;
        const uint32_t* bB_l = bA_h + 3 * ARRU32;

        #pragma unroll
        for (int ks = 0; ks < 2; ks++) {
            int kb = ks * 8;
            uint32_t Ahf[4][4], Alf[4][4], Bhf[4][2], Blf[4][2];
            #pragma unroll
            for (int mt = 0; mt < 4; mt++) {
                int m0 = mb + mt * 16 + gr;
                Ahf[mt][0] = bA_h[(kb + gc) * SPITCH + m0];
                Ahf[mt][1] = bA_h[(kb + gc) * SPITCH + m0 + 8];
                Ahf[mt][2] = bA_h[(kb + gc + 4) * SPITCH + m0];
                Ahf[mt][3] = bA_h[(kb + gc + 4) * SPITCH + m0 + 8];
                Alf[mt][0] = bA_l[(kb + gc) * SPITCH + m0];
                Alf[mt][1] = bA_l[(kb + gc) * SPITCH + m0 + 8];
                Alf[mt][2] = bA_l[(kb + gc + 4) * SPITCH + m0];
                Alf[mt][3] = bA_l[(kb + gc + 4) * SPITCH + m0 + 8];
            }
            #pragma unroll
            for (int nt = 0; nt < 4; nt++) {
                int n0 = nb + nt * 8 + gr;
                Bhf[nt][0] = bB_h[(kb + gc) * SPITCH + n0];
                Bhf[nt][1] = bB_h[(kb + gc + 4) * SPITCH + n0];
                Blf[nt][0] = bB_l[(kb + gc) * SPITCH + n0];
                Blf[nt][1] = bB_l[(kb + gc + 4) * SPITCH + n0];
            }
            #pragma unroll
            for (int mt = 0; mt < 4; mt++)
                #pragma unroll
                for (int nt = 0; nt < 4; nt++) {
                    MMA_BF16(acc[mt][nt], Ahf[mt][0], Ahf[mt][1], Ahf[mt][2], Ahf[mt][3],
                             Bhf[nt][0], Bhf[nt][1]);
                    MMA_BF16(acc[mt][nt], Ahf[mt][0], Ahf[mt][1], Ahf[mt][2], Ahf[mt][3],
                             Blf[nt][0], Blf[nt][1]);
                    MMA_BF16(acc[mt][nt], Alf[mt][0], Alf[mt][1], Alf[mt][2], Alf[mt][3],
                             Bhf[nt][0], Bhf[nt][1]);
                }
        }
        if (c + 1 < NC) STS_CHUNK((c + 1) & 1);
        __syncthreads();
    }

    // ---- epilogue ----
    #pragma unroll
    for (int nt = 0; nt < 4; nt++) {
        int nc = nb + nt * 8 + gc * 2;
        float2 bv = make_float2(bias_s[nc], bias_s[nc + 1]);
        int n0 = bn + nc;
        #pragma unroll
        for (int mt = 0; mt < 4; mt++) {
            int m0 = bm + mb + mt * 16 + gr;
            float v00 = tanhf(acc[mt][nt][0] + bv.x);
            float v01 = tanhf(acc[mt][nt][1] + bv.y);
            float v10 = tanhf(acc[mt][nt][2] + bv.x);
            float v11 = tanhf(acc[mt][nt][3] + bv.y);
            if (OUT_SPLIT) {
                __nv_bfloat16 h00 = __float2bfloat16_rn(v00);
                __nv_bfloat16 h01 = __float2bfloat16_rn(v01);
                __nv_bfloat16 h10 = __float2bfloat16_rn(v10);
                __nv_bfloat16 h11 = __float2bfloat16_rn(v11);
                *(__nv_bfloat162*)&Ch[(size_t)m0 * N + n0] = __nv_bfloat162(h00, h01);
                *(__nv_bfloat162*)&Ch[(size_t)(m0 + 8) * N + n0] = __nv_bfloat162(h10, h11);
                *(__nv_bfloat162*)&Cl[(size_t)m0 * N + n0] = __nv_bfloat162(
                    __float2bfloat16_rn(v00 - __bfloat162float(h00)),
                    __float2bfloat16_rn(v01 - __bfloat162float(h01)));
                *(__nv_bfloat162*)&Cl[(size_t)(m0 + 8) * N + n0] = __nv_bfloat162(
                    __float2bfloat16_rn(v10 - __bfloat162float(h10)),
                    __float2bfloat16_rn(v11 - __bfloat162float(h11)));
            } else {
                *(float2*)&C[(size_t)m0 * N + n0] = make_float2(v00, v01);
                *(float2*)&C[(size_t)(m0 + 8) * N + n0] = make_float2(v10, v11);
            }
        }
    }
}

// ================= decoder (with fused finalization) =================
__global__ void k_decode(const int* __restrict__ tuser, const int* __restrict__ titem,
                         const float* __restrict__ trating, const float* __restrict__ Wdec,
                         const float* __restrict__ bdec, float* __restrict__ out,
                         int nt, int write_loss) {
    int warp = threadIdx.x >> 5, lane = threadIdx.x & 31;
    int t = blockIdx.x * 8 + warp;
    __shared__ double part[8];
    double mine = 0.0;
    if (t < nt) {
        int u = tuser[t], it = titem[t];
        const float4* g = (const float4*)g_dec + (size_t)u * 128;
        const float4* w = (const float4*)Wdec + (size_t)it * 128;
        float s = 0.f;
        #pragma unroll
        for (int q = 0; q < 4; q++) {
            float4 a = g[q * 32 + lane];
            float4 b = w[q * 32 + lane];
            s = fmaf(a.x, b.x, s);
            s = fmaf(a.y, b.y, s);
            s = fmaf(a.z, b.z, s);
            s = fmaf(a.w, b.w, s);
        }
        #pragma unroll
        for (int o = 16; o; o >>= 1) s += __shfl_xor_sync(0xffffffff, s, o);
        if (lane == 0) {
            float pred = s + bdec[it];
            out[t] = pred;
            float d = pred - trating[t];
            mine = (double)d * (double)d;
        }
    }
    if (lane == 0) part[warp] = mine;
    __syncthreads();
    if (threadIdx.x == 0) {
        double ss = 0.0;
        #pragma unroll
        for (int i = 0; i < 8; i++) ss += part[i];
        atomicAdd(&g_loss, ss);
        __threadfence();
        int done = atomicAdd(&g_dcount, 1);
        if (done == (int)gridDim.x - 1) {
            g_dcount = 0;                                   // self-reset for next replay
            if (write_loss) out[nt] = (float)(g_loss / (double)nt);
        }
    }
}

// ================= launch =================
extern "C" void kernel_launch(void* const* d_in, const int* in_sizes, int n_in,
                              void* d_out, int out_size) {
    const int*   user    = (const int*)d_in[0];
    const int*   item    = (const int*)d_in[1];
    const float* rating  = (const float*)d_in[2];
    const int*   tuser   = (const int*)d_in[3];
    const int*   titem   = (const int*)d_in[4];
    const float* trating = (const float*)d_in[5];
    const float* W_enc   = (const float*)d_in[6];
    const float* b_enc   = (const float*)d_in[7];
    const float* W1      = (const float*)d_in[8];
    const float* b1      = (const float*)d_in[9];
    const float* W2      = (const float*)d_in[10];
    const float* b2      = (const float*)d_in[11];
    const float* W_dec   = (const float*)d_in[12];
    const float* b_dec   = (const float*)d_in[13];
    float* out = (float*)d_out;

    int N  = in_sizes[0];
    int NT = in_sizes[3];
    (void)n_in;

    void *cnt_ptr, *loss_ptr;
    void *xh_p, *xl_p, *ench_p, *encl_p, *w1h_p, *w1l_p, *w2h_p, *w2l_p, *dec_p;
    cudaGetSymbolAddress(&cnt_ptr, g_cnt);
    cudaGetSymbolAddress(&loss_ptr, g_loss);
    cudaGetSymbolAddress(&xh_p, g_xh);
    cudaGetSymbolAddress(&xl_p, g_xl);
    cudaGetSymbolAddress(&ench_p, g_ench);
    cudaGetSymbolAddress(&encl_p, g_encl);
    cudaGetSymbolAddress(&w1h_p, g_w1h);
    cudaGetSymbolAddress(&w1l_p, g_w1l);
    cudaGetSymbolAddress(&w2h_p, g_w2h);
    cudaGetSymbolAddress(&w2l_p, g_w2l);
    cudaGetSymbolAddress(&dec_p, g_dec);

    cudaFuncSetAttribute(k_gemm<0>, cudaFuncAttributeMaxDynamicSharedMemorySize, GEMM_SMEM);
    cudaFuncSetAttribute(k_gemm<1>, cudaFuncAttributeMaxDynamicSharedMemorySize, GEMM_SMEM);

    // zero counters + loss
    cudaMemsetAsync(cnt_ptr, 0, NUM_USERS * sizeof(int), 0);
    cudaMemsetAsync(loss_ptr, 0, sizeof(double), 0);
    // transpose W_enc
    {
        dim3 b(32, 8), g((NUM_ITEMS + 31) / 32, H0 / 32);
        k_transpose<<<g, b>>>(W_enc);
    }
    // split weights to bf16 hi/lo (W1: 32768 float4, W2: 32768 float4)
    k_convw<<<256, 256>>>(W1, W2);
    // counting sort by user
    k_hist<<<(N + 255) / 256, 256>>>(user, N);
    k_scan1<<<64, 256>>>();
    k_scan2<<<1, 64>>>(N);
    k_scan3<<<64, 256>>>();
    k_scatter<<<(N + 255) / 256, 256>>>(user, item, rating, N);
    // encoder aggregation + tanh -> bf16 hi/lo
    k_encode<<<NUM_USERS, 128>>>(b_enc);
    // MLP GEMMs
    {
        dim3 g1(LAT / 128, NUM_USERS / 128);
        k_gemm<1><<<g1, 256, GEMM_SMEM>>>(
            (const __nv_bfloat16*)xh_p, (const __nv_bfloat16*)xl_p,
            (const __nv_bfloat16*)w1h_p, (const __nv_bfloat16*)w1l_p,
            b1, nullptr, (__nv_bfloat16*)ench_p, (__nv_bfloat16*)encl_p,
            NUM_USERS, LAT, H0);
        dim3 g2(H0 / 128, NUM_USERS / 128);
        k_gemm<0><<<g2, 256, GEMM_SMEM>>>(
            (const __nv_bfloat16*)ench_p, (const __nv_bfloat16*)encl_p,
            (const __nv_bfloat16*)w2h_p, (const __nv_bfloat16*)w2l_p,
            b2, (float*)dec_p, nullptr, nullptr,
            NUM_USERS, H0, LAT);
    }
    // decoder + loss (finalization fused)
    k_decode<<<(NT + 7) / 8, 256>>>(tuser, titem, trating, W_dec, b_dec, out, NT,
                                    out_size > NT ? 1 : 0);
}

// round 6
// speedup vs baseline: 1.3298x; 1.0146x over previous
#include <cuda_runtime.h>
#include <cuda_bf16.h>
#include <math.h>
#include <stdint.h>

// ---- fixed problem shape ----
#define NUM_ITEMS 50000
#define NUM_USERS 16384
#define H0 512
#define LAT 256
#define NMAX 262144

// ---- scratch ----
static __device__ float  g_WencT[(size_t)NUM_ITEMS * H0];
static __device__ __nv_bfloat16 g_xh[(size_t)NUM_USERS * H0];
static __device__ __nv_bfloat16 g_xl[(size_t)NUM_USERS * H0];
static __device__ __nv_bfloat16 g_ench[(size_t)NUM_USERS * LAT];
static __device__ __nv_bfloat16 g_encl[(size_t)NUM_USERS * LAT];
static __device__ __nv_bfloat16 g_w1h[(size_t)LAT * H0];
static __device__ __nv_bfloat16 g_w1l[(size_t)LAT * H0];
static __device__ __nv_bfloat16 g_w2h[(size_t)H0 * LAT];
static __device__ __nv_bfloat16 g_w2l[(size_t)H0 * LAT];
static __device__ float  g_dec[(size_t)NUM_USERS * H0];
static __device__ int    g_cnt[NUM_USERS];
static __device__ int    g_off[NUM_USERS + 1];
static __device__ int    g_cur[NUM_USERS];
static __device__ int    g_pitem[NMAX];
static __device__ float  g_prate[NMAX];
static __device__ double g_part[NMAX / 32];
static __device__ int    g_dcount;

// ================= transpose W_enc + split W1/W2 (merged kernel) =================
__global__ void k_prep(const float* __restrict__ W, const float* __restrict__ W1,
                       const float* __restrict__ W2) {
    if (blockIdx.y < 16) {
        // transpose W_enc [H0, NUM_ITEMS] -> g_WencT [NUM_ITEMS, H0]
        __shared__ float tile[32][33];
        int t = threadIdx.x;
        int tx = t & 31, ty = t >> 5;                      // (32, 8)
        int col0 = blockIdx.x * 32;
        int row0 = blockIdx.y * 32;
        #pragma unroll
        for (int j = 0; j < 4; j++) {
            int r = ty + j * 8, c = col0 + tx;
            if (c < NUM_ITEMS) tile[r][tx] = W[(size_t)(row0 + r) * NUM_ITEMS + c];
        }
        __syncthreads();
        #pragma unroll
        for (int j = 0; j < 4; j++) {
            int i = col0 + ty + j * 8, h = row0 + tx;
            if (i < NUM_ITEMS) g_WencT[(size_t)i * H0 + h] = tile[tx][ty + j * 8];
        }
    } else {
        // split W1 / W2 into bf16 hi/lo
        int i = blockIdx.x * blockDim.x + threadIdx.x;     // float4 units
        const int n1 = LAT * H0 / 4;                       // 32768
        if (i >= 2 * n1) return;
        const float* src; __nv_bfloat16 *dh, *dl; int j;
        if (i < n1) { src = W1; dh = g_w1h; dl = g_w1l; j = i; }
        else        { src = W2; dh = g_w2h; dl = g_w2l; j = i - n1; }
        float4 v = ((const float4*)src)[j];
        __nv_bfloat16 hx = __float2bfloat16_rn(v.x);
        __nv_bfloat16 hy = __float2bfloat16_rn(v.y);
        __nv_bfloat16 hz = __float2bfloat16_rn(v.z);
        __nv_bfloat16 hw = __float2bfloat16_rn(v.w);
        ((__nv_bfloat162*)dh)[j * 2 + 0] = __nv_bfloat162(hx, hy);
        ((__nv_bfloat162*)dh)[j * 2 + 1] = __nv_bfloat162(hz, hw);
        ((__nv_bfloat162*)dl)[j * 2 + 0] = __nv_bfloat162(
            __float2bfloat16_rn(v.x - __bfloat162float(hx)),
            __float2bfloat16_rn(v.y - __bfloat162float(hy)));
        ((__nv_bfloat162*)dl)[j * 2 + 1] = __nv_bfloat162(
            __float2bfloat16_rn(v.z - __bfloat162float(hz)),
            __float2bfloat16_rn(v.w - __bfloat162float(hw)));
    }
}

// ================= counting sort =================
__global__ void k_hist(const int* __restrict__ user, int n) {
    int i = blockIdx.x * blockDim.x + threadIdx.x;
    if (i < n) atomicAdd(&g_cnt[user[i]], 1);
}

// fused exclusive scan over 16384 counts (single block, 1024 threads, shuffle)
__global__ void k_scan(int n) {
    int t = threadIdx.x;
    int lane = t & 31, wid = t >> 5;
    int base = t * 16;
    int local[16];
    int s = 0;
    #pragma unroll
    for (int i = 0; i < 16; i++) { local[i] = g_cnt[base + i]; s += local[i]; }
    int v = s;
    #pragma unroll
    for (int o = 1; o < 32; o <<= 1) {
        int u = __shfl_up_sync(0xffffffffu, v, o);
        if (lane >= o) v += u;
    }
    __shared__ int wsum[32];
    if (lane == 31) wsum[wid] = v;
    __syncthreads();
    if (wid == 0) {
        int w = wsum[lane];
        #pragma unroll
        for (int o = 1; o < 32; o <<= 1) {
            int u = __shfl_up_sync(0xffffffffu, w, o);
            if (lane >= o) w += u;
        }
        wsum[lane] = w;
    }
    __syncthreads();
    int run = (wid ? wsum[wid - 1] : 0) + (v - s);
    #pragma unroll
    for (int i = 0; i < 16; i++) {
        g_off[base + i] = run;
        g_cur[base + i] = run;
        run += local[i];
    }
    if (t == 1023) g_off[NUM_USERS] = n;
}

__global__ void k_scatter(const int* __restrict__ user, const int* __restrict__ item,
                          const float* __restrict__ rating, int n) {
    int i = blockIdx.x * blockDim.x + threadIdx.x;
    if (i < n) {
        int p = atomicAdd(&g_cur[user[i]], 1);
        g_pitem[p] = item[i];
        g_prate[p] = rating[i];
    }
}

// ================= encoder aggregation + tanh -> bf16 hi/lo =================
__global__ void k_encode(const float* __restrict__ b_enc) {
    int u = blockIdx.x;
    int t = threadIdx.x;                                   // 128
    int s = g_off[u], e = g_off[u + 1];
    const float4* WT4 = (const float4*)g_WencT;
    float4 acc0 = make_float4(0.f, 0.f, 0.f, 0.f);
    float4 acc1 = make_float4(0.f, 0.f, 0.f, 0.f);
    __shared__ int   sit[128];
    __shared__ float srt[128];
    for (int j0 = s; j0 < e; j0 += 128) {
        int c = min(128, e - j0);
        if (t < c) { sit[t] = g_pitem[j0 + t]; srt[t] = g_prate[j0 + t]; }
        __syncthreads();
        int q = 0;
        for (; q + 1 < c; q += 2) {
            int i0 = sit[q], i1 = sit[q + 1];
            float r0 = srt[q], r1 = srt[q + 1];
            float4 w0 = WT4[(size_t)i0 * 128 + t];
            float4 w1 = WT4[(size_t)i1 * 128 + t];
            acc0.x = fmaf(r0, w0.x, acc0.x); acc1.x = fmaf(r1, w1.x, acc1.x);
            acc0.y = fmaf(r0, w0.y, acc0.y); acc1.y = fmaf(r1, w1.y, acc1.y);
            acc0.z = fmaf(r0, w0.z, acc0.z); acc1.z = fmaf(r1, w1.z, acc1.z);
            acc0.w = fmaf(r0, w0.w, acc0.w); acc1.w = fmaf(r1, w1.w, acc1.w);
        }
        if (q < c) {
            int i0 = sit[q]; float r0 = srt[q];
            float4 w0 = WT4[(size_t)i0 * 128 + t];
            acc0.x = fmaf(r0, w0.x, acc0.x);
            acc0.y = fmaf(r0, w0.y, acc0.y);
            acc0.z = fmaf(r0, w0.z, acc0.z);
            acc0.w = fmaf(r0, w0.w, acc0.w);
        }
        __syncthreads();
    }
    float4 b = ((const float4*)b_enc)[t];
    float vx = tanhf(acc0.x + acc1.x + b.x);
    float vy = tanhf(acc0.y + acc1.y + b.y);
    float vz = tanhf(acc0.z + acc1.z + b.z);
    float vw = tanhf(acc0.w + acc1.w + b.w);
    __nv_bfloat16 hx = __float2bfloat16_rn(vx);
    __nv_bfloat16 hy = __float2bfloat16_rn(vy);
    __nv_bfloat16 hz = __float2bfloat16_rn(vz);
    __nv_bfloat16 hw = __float2bfloat16_rn(vw);
    size_t o2 = (size_t)u * 256 + t * 2;
    ((__nv_bfloat162*)g_xh)[o2 + 0] = __nv_bfloat162(hx, hy);
    ((__nv_bfloat162*)g_xh)[o2 + 1] = __nv_bfloat162(hz, hw);
    ((__nv_bfloat162*)g_xl)[o2 + 0] = __nv_bfloat162(
        __float2bfloat16_rn(vx - __bfloat162float(hx)),
        __float2bfloat16_rn(vy - __bfloat162float(hy)));
    ((__nv_bfloat162*)g_xl)[o2 + 1] = __nv_bfloat162(
        __float2bfloat16_rn(vz - __bfloat162float(hz)),
        __float2bfloat16_rn(vw - __bfloat162float(hw)));
}

// ================= bf16 3-way-split GEMM, k-chunk 16, occupancy 2 =================
#define MMA_BF16(c, a0, a1, a2, a3, b0, b1)                                         \
    asm volatile("mma.sync.aligned.m16n8k16.row.col.f32.bf16.bf16.f32 "             \
                 "{%0,%1,%2,%3},{%4,%5,%6,%7},{%8,%9},{%0,%1,%2,%3};"               \
                 : "+f"(c[0]), "+f"(c[1]), "+f"(c[2]), "+f"(c[3])                   \
                 : "r"(a0), "r"(a1), "r"(a2), "r"(a3), "r"(b0), "r"(b1))

#define SPITCH 136
#define ARRU32 (8 * SPITCH)         // one [k2][row] slab (k2 = 0..7)
#define BUFU32 (4 * ARRU32)         // Ah, Al, Bh, Bl
#define GEMM_SMEM ((2 * BUFU32 + 128) * 4)

template <int OUT_SPLIT>
__global__ void __launch_bounds__(256, 2)
k_gemm(const __nv_bfloat16* __restrict__ Ah_g, const __nv_bfloat16* __restrict__ Al_g,
       const __nv_bfloat16* __restrict__ Bh_g, const __nv_bfloat16* __restrict__ Bl_g,
       const float* __restrict__ bias, float* __restrict__ C,
       __nv_bfloat16* __restrict__ Ch, __nv_bfloat16* __restrict__ Cl,
       int M, int N, int K) {
    extern __shared__ uint32_t sm[];
    float* bias_s = (float*)(sm + 2 * BUFU32);

    int tid = threadIdx.x;
    int lane = tid & 31;
    int wid = tid >> 5;
    int warp_m = wid & 1;
    int warp_n = wid >> 1;
    int gr = lane >> 2;
    int gc = lane & 3;

    int bm = blockIdx.y * 128;
    int bn = blockIdx.x * 128;

    if (tid < 128) bias_s[tid] = bias[bn + tid];

    float acc[4][4][4];
    #pragma unroll
    for (int i = 0; i < 4; i++)
        #pragma unroll
        for (int j = 0; j < 4; j++)
            #pragma unroll
            for (int q = 0; q < 4; q++) acc[i][j][q] = 0.f;

    const int mb = warp_m * 64;
    const int nb = warp_n * 32;
    const int r    = tid >> 1;       // row within tile
    const int half = tid & 1;        // which 8-wide k half of the 16 chunk
    const int kb2  = half * 4;       // k2 base for STS

    const __nv_bfloat16* pAh = Ah_g + (size_t)(bm + r) * K + half * 8;
    const __nv_bfloat16* pAl = Al_g + (size_t)(bm + r) * K + half * 8;
    const __nv_bfloat16* pBh = Bh_g + (size_t)(bn + r) * K + half * 8;
    const __nv_bfloat16* pBl = Bl_g + (size_t)(bn + r) * K + half * 8;

    uint4 rAh, rAl, rBh, rBl;

#define LDG_CHUNK(k0)                                                   \
    do {                                                                \
        rAh = *(const uint4*)(pAh + (k0));                              \
        rAl = *(const uint4*)(pAl + (k0));                              \
        rBh = *(const uint4*)(pBh + (k0));                              \
        rBl = *(const uint4*)(pBl + (k0));                              \
    } while (0)

#define STS_CHUNK(buf)                                                  \
    do {                                                                \
        uint32_t* b0 = sm + (buf) * BUFU32;                             \
        uint32_t* b1 = b0 + ARRU32;                                     \
        uint32_t* b2 = b0 + 2 * ARRU32;                                 \
        uint32_t* b3 = b0 + 3 * ARRU32;                                 \
        b0[(kb2 + 0) * SPITCH + r] = rAh.x;                             \
        b0[(kb2 + 1) * SPITCH + r] = rAh.y;                             \
        b0[(kb2 + 2) * SPITCH + r] = rAh.z;                             \
        b0[(kb2 + 3) * SPITCH + r] = rAh.w;                             \
        b1[(kb2 + 0) * SPITCH + r] = rAl.x;                             \
        b1[(kb2 + 1) * SPITCH + r] = rAl.y;                             \
        b1[(kb2 + 2) * SPITCH + r] = rAl.z;                             \
        b1[(kb2 + 3) * SPITCH + r] = rAl.w;                             \
        b2[(kb2 + 0) * SPITCH + r] = rBh.x;                             \
        b2[(kb2 + 1) * SPITCH + r] = rBh.y;                             \
        b2[(kb2 + 2) * SPITCH + r] = rBh.z;                             \
        b2[(kb2 + 3) * SPITCH + r] = rBh.w;                             \
        b3[(kb2 + 0) * SPITCH + r] = rBl.x;                             \
        b3[(kb2 + 1) * SPITCH + r] = rBl.y;                             \
        b3[(kb2 + 2) * SPITCH + r] = rBl.z;                             \
        b3[(kb2 + 3) * SPITCH + r] = rBl.w;                             \
    } while (0)

    const int NC = K / 16;
    LDG_CHUNK(0);
    STS_CHUNK(0);
    __syncthreads();

    for (int c = 0; c < NC; c++) {
        if (c + 1 < NC) LDG_CHUNK((c + 1) * 16);

        const uint32_t* bAh = sm + (c & 1) * BUFU32;
        const uint32_t* bAl = bAh + ARRU32;
        const uint32_t* bBh = bAh + 2 * ARRU32;
        const uint32_t* bBl = bAh + 3 * ARRU32;

        uint32_t Bhf[4][2], Blf[4][2];
        #pragma unroll
        for (int nt = 0; nt < 4; nt++) {
            int n0 = nb + nt * 8 + gr;
            Bhf[nt][0] = bBh[gc * SPITCH + n0];
            Bhf[nt][1] = bBh[(gc + 4) * SPITCH + n0];
            Blf[nt][0] = bBl[gc * SPITCH + n0];
            Blf[nt][1] = bBl[(gc + 4) * SPITCH + n0];
        }
        #pragma unroll
        for (int mt = 0; mt < 4; mt++) {
            int m0 = mb + mt * 16 + gr;
            uint32_t Ahf[4], Alf[4];
            Ahf[0] = bAh[gc * SPITCH + m0];
            Ahf[1] = bAh[gc * SPITCH + m0 + 8];
            Ahf[2] = bAh[(gc + 4) * SPITCH + m0];
            Ahf[3] = bAh[(gc + 4) * SPITCH + m0 + 8];
            Alf[0] = bAl[gc * SPITCH + m0];
            Alf[1] = bAl[gc * SPITCH + m0 + 8];
            Alf[2] = bAl[(gc + 4) * SPITCH + m0];
            Alf[3] = bAl[(gc + 4) * SPITCH + m0 + 8];
            #pragma unroll
            for (int nt = 0; nt < 4; nt++) {
                MMA_BF16(acc[mt][nt], Ahf[0], Ahf[1], Ahf[2], Ahf[3],
                         Bhf[nt][0], Bhf[nt][1]);
                MMA_BF16(acc[mt][nt], Ahf[0], Ahf[1], Ahf[2], Ahf[3],
                         Blf[nt][0], Blf[nt][1]);
                MMA_BF16(acc[mt][nt], Alf[0], Alf[1], Alf[2], Alf[3],
                         Bhf[nt][0], Bhf[nt][1]);
            }
        }
        if (c + 1 < NC) STS_CHUNK((c + 1) & 1);
        __syncthreads();
    }

    // ---- epilogue ----
    #pragma unroll
    for (int nt = 0; nt < 4; nt++) {
        int nc = nb + nt * 8 + gc * 2;
        float2 bv = make_float2(bias_s[nc], bias_s[nc + 1]);
        int n0 = bn + nc;
        #pragma unroll
        for (int mt = 0; mt < 4; mt++) {
            int m0 = bm + mb + mt * 16 + gr;
            float v00 = tanhf(acc[mt][nt][0] + bv.x);
            float v01 = tanhf(acc[mt][nt][1] + bv.y);
            float v10 = tanhf(acc[mt][nt][2] + bv.x);
            float v11 = tanhf(acc[mt][nt][3] + bv.y);
            if (OUT_SPLIT) {
                __nv_bfloat16 h00 = __float2bfloat16_rn(v00);
                __nv_bfloat16 h01 = __float2bfloat16_rn(v01);
                __nv_bfloat16 h10 = __float2bfloat16_rn(v10);
                __nv_bfloat16 h11 = __float2bfloat16_rn(v11);
                *(__nv_bfloat162*)&Ch[(size_t)m0 * N + n0] = __nv_bfloat162(h00, h01);
                *(__nv_bfloat162*)&Ch[(size_t)(m0 + 8) * N + n0] = __nv_bfloat162(h10, h11);
                *(__nv_bfloat162*)&Cl[(size_t)m0 * N + n0] = __nv_bfloat162(
                    __float2bfloat16_rn(v00 - __bfloat162float(h00)),
                    __float2bfloat16_rn(v01 - __bfloat162float(h01)));
                *(__nv_bfloat162*)&Cl[(size_t)(m0 + 8) * N + n0] = __nv_bfloat162(
                    __float2bfloat16_rn(v10 - __bfloat162float(h10)),
                    __float2bfloat16_rn(v11 - __bfloat162float(h11)));
            } else {
                *(float2*)&C[(size_t)m0 * N + n0] = make_float2(v00, v01);
                *(float2*)&C[(size_t)(m0 + 8) * N + n0] = make_float2(v10, v11);
            }
        }
    }
}

// ================= decoder: 4 targets/warp, array partials, fused final =================
__global__ void k_decode(const int* __restrict__ tuser, const int* __restrict__ titem,
                         const float* __restrict__ trating, const float* __restrict__ Wdec,
                         const float* __restrict__ bdec, float* __restrict__ out,
                         int nt, int write_loss) {
    int warp = threadIdx.x >> 5, lane = threadIdx.x & 31;
    int base = blockIdx.x * 32 + warp * 4;
    double mine = 0.0;
    #pragma unroll
    for (int p = 0; p < 2; p++) {
        int t0 = base + p * 2;
        int t1 = t0 + 1;
        bool v0 = t0 < nt, v1 = t1 < nt;
        float s0 = 0.f, s1 = 0.f;
        int u0 = 0, i0 = 0, u1 = 0, i1 = 0;
        if (v0) { u0 = tuser[t0]; i0 = titem[t0]; }
        if (v1) { u1 = tuser[t1]; i1 = titem[t1]; }
        const float4* ga = (const float4*)g_dec + (size_t)u0 * 128;
        const float4* wa = (const float4*)Wdec + (size_t)i0 * 128;
        const float4* gb = (const float4*)g_dec + (size_t)u1 * 128;
        const float4* wb = (const float4*)Wdec + (size_t)i1 * 128;
        #pragma unroll
        for (int q = 0; q < 4; q++) {
            if (v0) {
                float4 a = ga[q * 32 + lane];
                float4 b = wa[q * 32 + lane];
                s0 = fmaf(a.x, b.x, s0);
                s0 = fmaf(a.y, b.y, s0);
                s0 = fmaf(a.z, b.z, s0);
                s0 = fmaf(a.w, b.w, s0);
            }
            if (v1) {
                float4 a = gb[q * 32 + lane];
                float4 b = wb[q * 32 + lane];
                s1 = fmaf(a.x, b.x, s1);
                s1 = fmaf(a.y, b.y, s1);
                s1 = fmaf(a.z, b.z, s1);
                s1 = fmaf(a.w, b.w, s1);
            }
        }
        #pragma unroll
        for (int o = 16; o; o >>= 1) {
            s0 += __shfl_xor_sync(0xffffffffu, s0, o);
            s1 += __shfl_xor_sync(0xffffffffu, s1, o);
        }
        if (lane == 0) {
            if (v0) {
                float pred = s0 + bdec[i0];
                out[t0] = pred;
                float d = pred - trating[t0];
                mine += (double)d * (double)d;
            }
            if (v1) {
                float pred = s1 + bdec[i1];
                out[t1] = pred;
                float d = pred - trating[t1];
                mine += (double)d * (double)d;
            }
        }
    }
    __shared__ double part_s[8];
    __shared__ int is_last;
    if (lane == 0) part_s[warp] = mine;
    __syncthreads();
    if (threadIdx.x == 0) {
        double ss = 0.0;
        #pragma unroll
        for (int i = 0; i < 8; i++) ss += part_s[i];
        g_part[blockIdx.x] = ss;
        __threadfence();
        int done = atomicAdd(&g_dcount, 1);
        is_last = (done == (int)gridDim.x - 1);
        if (is_last) g_dcount = 0;                          // self-reset for replay
    }
    __syncthreads();
    if (is_last) {
        int nb = (int)gridDim.x;
        double s = 0.0;
        for (int i = threadIdx.x; i < nb; i += 256) s += g_part[i];
        // block reduce 256 doubles
        __shared__ double red[8];
        #pragma unroll
        for (int o = 16; o; o >>= 1) s += __shfl_xor_sync(0xffffffffu, s, o);
        if (lane == 0) red[warp] = s;
        __syncthreads();
        if (threadIdx.x == 0) {
            double tot = 0.0;
            #pragma unroll
            for (int i = 0; i < 8; i++) tot += red[i];
            if (write_loss) out[nt] = (float)(tot / (double)nt);
        }
    }
}

// ================= launch =================
extern "C" void kernel_launch(void* const* d_in, const int* in_sizes, int n_in,
                              void* d_out, int out_size) {
    const int*   user    = (const int*)d_in[0];
    const int*   item    = (const int*)d_in[1];
    const float* rating  = (const float*)d_in[2];
    const int*   tuser   = (const int*)d_in[3];
    const int*   titem   = (const int*)d_in[4];
    const float* trating = (const float*)d_in[5];
    const float* W_enc   = (const float*)d_in[6];
    const float* b_enc   = (const float*)d_in[7];
    const float* W1      = (const float*)d_in[8];
    const float* b1      = (const float*)d_in[9];
    const float* W2      = (const float*)d_in[10];
    const float* b2      = (const float*)d_in[11];
    const float* W_dec   = (const float*)d_in[12];
    const float* b_dec   = (const float*)d_in[13];
    float* out = (float*)d_out;

    int N  = in_sizes[0];
    int NT = in_sizes[3];
    (void)n_in;

    void *cnt_ptr, *xh_p, *xl_p, *ench_p, *encl_p, *w1h_p, *w1l_p, *w2h_p, *w2l_p, *dec_p;
    cudaGetSymbolAddress(&cnt_ptr, g_cnt);
    cudaGetSymbolAddress(&xh_p, g_xh);
    cudaGetSymbolAddress(&xl_p, g_xl);
    cudaGetSymbolAddress(&ench_p, g_ench);
    cudaGetSymbolAddress(&encl_p, g_encl);
    cudaGetSymbolAddress(&w1h_p, g_w1h);
    cudaGetSymbolAddress(&w1l_p, g_w1l);
    cudaGetSymbolAddress(&w2h_p, g_w2h);
    cudaGetSymbolAddress(&w2l_p, g_w2l);
    cudaGetSymbolAddress(&dec_p, g_dec);

    cudaFuncSetAttribute(k_gemm<0>, cudaFuncAttributeMaxDynamicSharedMemorySize, GEMM_SMEM);
    cudaFuncSetAttribute(k_gemm<1>, cudaFuncAttributeMaxDynamicSharedMemorySize, GEMM_SMEM);

    // 0: zero counters
    cudaMemsetAsync(cnt_ptr, 0, NUM_USERS * sizeof(int), 0);
    // 1: transpose W_enc + split W1/W2
    {
        dim3 g((NUM_ITEMS + 31) / 32, 17);
        k_prep<<<g, 256>>>(W_enc, W1, W2);
    }
    // 2-4: counting sort by user
    k_hist<<<(N + 255) / 256, 256>>>(user, N);
    k_scan<<<1, 1024>>>(N);
    k_scatter<<<(N + 255) / 256, 256>>>(user, item, rating, N);
    // 5: encoder aggregation + tanh -> bf16 hi/lo (profiled launch)
    k_encode<<<NUM_USERS, 128>>>(b_enc);
    // 6-7: MLP GEMMs
    {
        dim3 g1(LAT / 128, NUM_USERS / 128);
        k_gemm<1><<<g1, 256, GEMM_SMEM>>>(
            (const __nv_bfloat16*)xh_p, (const __nv_bfloat16*)xl_p,
            (const __nv_bfloat16*)w1h_p, (const __nv_bfloat16*)w1l_p,
            b1, nullptr, (__nv_bfloat16*)ench_p, (__nv_bfloat16*)encl_p,
            NUM_USERS, LAT, H0);
        dim3 g2(H0 / 128, NUM_USERS / 128);
        k_gemm<0><<<g2, 256, GEMM_SMEM>>>(
            (const __nv_bfloat16*)ench_p, (const __nv_bfloat16*)encl_p,
            (const __nv_bfloat16*)w2h_p, (const __nv_bfloat16*)w2l_p,
            b2, (float*)dec_p, nullptr, nullptr,
            NUM_USERS, H0, LAT);
    }
    // 8: decoder + loss (finalization fused, partial-array reduction)
    k_decode<<<(NT + 31) / 32, 256>>>(tuser, titem, trating, W_dec, b_dec, out, NT,
                                      out_size > NT ? 1 : 0);
}

// round 7
// speedup vs baseline: 1.4905x; 1.1209x over previous
#include <cuda_runtime.h>
#include <cuda_bf16.h>
#include <cuda_fp16.h>
#include <math.h>
#include <stdint.h>

// ---- fixed problem shape ----
#define NUM_ITEMS 50000
#define NUM_USERS 16384
#define H0 512
#define LAT 256
#define NMAX 262144

// ---- scratch ----
static __device__ __half g_WencT[(size_t)NUM_ITEMS * H0];    // fp16 [items, H0]
static __device__ __half g_wdh[(size_t)NUM_ITEMS * H0];      // fp16 Wdec [items, H0]
static __device__ __nv_bfloat16 g_xh[(size_t)NUM_USERS * H0];
static __device__ __nv_bfloat16 g_xl[(size_t)NUM_USERS * H0];
static __device__ __nv_bfloat16 g_ench[(size_t)NUM_USERS * LAT];
static __device__ __nv_bfloat16 g_encl[(size_t)NUM_USERS * LAT];
static __device__ __nv_bfloat16 g_w1h[(size_t)LAT * H0];
static __device__ __nv_bfloat16 g_w1l[(size_t)LAT * H0];
static __device__ __nv_bfloat16 g_w2h[(size_t)H0 * LAT];
static __device__ __nv_bfloat16 g_w2l[(size_t)H0 * LAT];
static __device__ __half g_dec[(size_t)NUM_USERS * H0];      // fp16 decoded
static __device__ int    g_cnt[NUM_USERS];
static __device__ int    g_off[NUM_USERS + 1];
static __device__ int    g_cur[NUM_USERS];
static __device__ int    g_pitem[NMAX];
static __device__ float  g_prate[NMAX];
static __device__ double g_part[NMAX / 32];
static __device__ int    g_dcount;

// ================= prep: transpose W_enc (fp16) + split W1/W2 + Wdec->fp16 =================
__global__ void k_prep(const float* __restrict__ W, const float* __restrict__ W1,
                       const float* __restrict__ W2, const float* __restrict__ Wdec) {
    int by = blockIdx.y;
    if (by < 16) {
        // transpose W_enc [H0, NUM_ITEMS] -> g_WencT [NUM_ITEMS, H0] (fp16)
        __shared__ float tile[32][33];
        int t = threadIdx.x;
        int tx = t & 31, ty = t >> 5;                      // (32, 8)
        int col0 = blockIdx.x * 32;
        int row0 = by * 32;
        #pragma unroll
        for (int j = 0; j < 4; j++) {
            int r = ty + j * 8, c = col0 + tx;
            if (c < NUM_ITEMS) tile[r][tx] = W[(size_t)(row0 + r) * NUM_ITEMS + c];
        }
        __syncthreads();
        #pragma unroll
        for (int j = 0; j < 4; j++) {
            int i = col0 + ty + j * 8, h = row0 + tx;
            if (i < NUM_ITEMS)
                g_WencT[(size_t)i * H0 + h] = __float2half_rn(tile[tx][ty + j * 8]);
        }
    } else if (by == 16) {
        // split W1 / W2 into bf16 hi/lo
        int i = blockIdx.x * blockDim.x + threadIdx.x;     // float4 units
        const int n1 = LAT * H0 / 4;                       // 32768
        if (i >= 2 * n1) return;
        const float* src; __nv_bfloat16 *dh, *dl; int j;
        if (i < n1) { src = W1; dh = g_w1h; dl = g_w1l; j = i; }
        else        { src = W2; dh = g_w2h; dl = g_w2l; j = i - n1; }
        float4 v = ((const float4*)src)[j];
        __nv_bfloat16 hx = __float2bfloat16_rn(v.x);
        __nv_bfloat16 hy = __float2bfloat16_rn(v.y);
        __nv_bfloat16 hz = __float2bfloat16_rn(v.z);
        __nv_bfloat16 hw = __float2bfloat16_rn(v.w);
        ((__nv_bfloat162*)dh)[j * 2 + 0] = __nv_bfloat162(hx, hy);
        ((__nv_bfloat162*)dh)[j * 2 + 1] = __nv_bfloat162(hz, hw);
        ((__nv_bfloat162*)dl)[j * 2 + 0] = __nv_bfloat162(
            __float2bfloat16_rn(v.x - __bfloat162float(hx)),
            __float2bfloat16_rn(v.y - __bfloat162float(hy)));
        ((__nv_bfloat162*)dl)[j * 2 + 1] = __nv_bfloat162(
            __float2bfloat16_rn(v.z - __bfloat162float(hz)),
            __float2bfloat16_rn(v.w - __bfloat162float(hw)));
    } else {
        // Wdec fp32 -> fp16 (25.6M floats = 6.4M float4, 16 y-rows)
        int idx = ((by - 17) * (int)gridDim.x + blockIdx.x) * 256 + threadIdx.x;
        if (idx >= NUM_ITEMS * H0 / 4) return;
        float4 v = ((const float4*)Wdec)[idx];
        ((__half2*)g_wdh)[idx * 2 + 0] = __floats2half2_rn(v.x, v.y);
        ((__half2*)g_wdh)[idx * 2 + 1] = __floats2half2_rn(v.z, v.w);
    }
}

// ================= counting sort =================
__global__ void k_hist(const int* __restrict__ user, int n) {
    int i = blockIdx.x * blockDim.x + threadIdx.x;
    if (i < n) atomicAdd(&g_cnt[user[i]], 1);
}

__global__ void k_scan(int n) {
    int t = threadIdx.x;
    int lane = t & 31, wid = t >> 5;
    int base = t * 16;
    int local[16];
    int s = 0;
    #pragma unroll
    for (int i = 0; i < 16; i++) { local[i] = g_cnt[base + i]; s += local[i]; }
    int v = s;
    #pragma unroll
    for (int o = 1; o < 32; o <<= 1) {
        int u = __shfl_up_sync(0xffffffffu, v, o);
        if (lane >= o) v += u;
    }
    __shared__ int wsum[32];
    if (lane == 31) wsum[wid] = v;
    __syncthreads();
    if (wid == 0) {
        int w = wsum[lane];
        #pragma unroll
        for (int o = 1; o < 32; o <<= 1) {
            int u = __shfl_up_sync(0xffffffffu, w, o);
            if (lane >= o) w += u;
        }
        wsum[lane] = w;
    }
    __syncthreads();
    int run = (wid ? wsum[wid - 1] : 0) + (v - s);
    #pragma unroll
    for (int i = 0; i < 16; i++) {
        g_off[base + i] = run;
        g_cur[base + i] = run;
        run += local[i];
    }
    if (t == 1023) g_off[NUM_USERS] = n;
}

__global__ void k_scatter(const int* __restrict__ user, const int* __restrict__ item,
                          const float* __restrict__ rating, int n) {
    int i = blockIdx.x * blockDim.x + threadIdx.x;
    if (i < n) {
        int p = atomicAdd(&g_cur[user[i]], 1);
        g_pitem[p] = item[i];
        g_prate[p] = rating[i];
    }
}

// ================= encoder aggregation (fp16 gathers, fp32 accum) =================
__global__ void k_encode(const float* __restrict__ b_enc) {
    int u = blockIdx.x;
    int t = threadIdx.x;                                   // 128; each handles 4 h
    int s = g_off[u], e = g_off[u + 1];
    const uint2* WT = (const uint2*)g_WencT;               // 4 halves per uint2, 128 per row
    float4 acc0 = make_float4(0.f, 0.f, 0.f, 0.f);
    float4 acc1 = make_float4(0.f, 0.f, 0.f, 0.f);
    __shared__ int   sit[128];
    __shared__ float srt[128];
    for (int j0 = s; j0 < e; j0 += 128) {
        int c = min(128, e - j0);
        if (t < c) { sit[t] = g_pitem[j0 + t]; srt[t] = g_prate[j0 + t]; }
        __syncthreads();
        int q = 0;
        for (; q + 1 < c; q += 2) {
            int i0 = sit[q], i1 = sit[q + 1];
            float r0 = srt[q], r1 = srt[q + 1];
            uint2 w0 = WT[(size_t)i0 * 128 + t];
            uint2 w1 = WT[(size_t)i1 * 128 + t];
            float2 a = __half22float2(*(__half2*)&w0.x);
            float2 b = __half22float2(*(__half2*)&w0.y);
            float2 cc = __half22float2(*(__half2*)&w1.x);
            float2 d = __half22float2(*(__half2*)&w1.y);
            acc0.x = fmaf(r0, a.x, acc0.x); acc1.x = fmaf(r1, cc.x, acc1.x);
            acc0.y = fmaf(r0, a.y, acc0.y); acc1.y = fmaf(r1, cc.y, acc1.y);
            acc0.z = fmaf(r0, b.x, acc0.z); acc1.z = fmaf(r1, d.x, acc1.z);
            acc0.w = fmaf(r0, b.y, acc0.w); acc1.w = fmaf(r1, d.y, acc1.w);
        }
        if (q < c) {
            int i0 = sit[q]; float r0 = srt[q];
            uint2 w0 = WT[(size_t)i0 * 128 + t];
            float2 a = __half22float2(*(__half2*)&w0.x);
            float2 b = __half22float2(*(__half2*)&w0.y);
            acc0.x = fmaf(r0, a.x, acc0.x);
            acc0.y = fmaf(r0, a.y, acc0.y);
            acc0.z = fmaf(r0, b.x, acc0.z);
            acc0.w = fmaf(r0, b.y, acc0.w);
        }
        __syncthreads();
    }
    float4 b = ((const float4*)b_enc)[t];
    float vx = tanhf(acc0.x + acc1.x + b.x);
    float vy = tanhf(acc0.y + acc1.y + b.y);
    float vz = tanhf(acc0.z + acc1.z + b.z);
    float vw = tanhf(acc0.w + acc1.w + b.w);
    __nv_bfloat16 hx = __float2bfloat16_rn(vx);
    __nv_bfloat16 hy = __float2bfloat16_rn(vy);
    __nv_bfloat16 hz = __float2bfloat16_rn(vz);
    __nv_bfloat16 hw = __float2bfloat16_rn(vw);
    size_t o2 = (size_t)u * 256 + t * 2;
    ((__nv_bfloat162*)g_xh)[o2 + 0] = __nv_bfloat162(hx, hy);
    ((__nv_bfloat162*)g_xh)[o2 + 1] = __nv_bfloat162(hz, hw);
    ((__nv_bfloat162*)g_xl)[o2 + 0] = __nv_bfloat162(
        __float2bfloat16_rn(vx - __bfloat162float(hx)),
        __float2bfloat16_rn(vy - __bfloat162float(hy)));
    ((__nv_bfloat162*)g_xl)[o2 + 1] = __nv_bfloat162(
        __float2bfloat16_rn(vz - __bfloat162float(hz)),
        __float2bfloat16_rn(vw - __bfloat162float(hw)));
}

// ================= bf16 3-way-split GEMM, k-chunk 16, occupancy 2 =================
#define MMA_BF16(c, a0, a1, a2, a3, b0, b1)                                         \
    asm volatile("mma.sync.aligned.m16n8k16.row.col.f32.bf16.bf16.f32 "             \
                 "{%0,%1,%2,%3},{%4,%5,%6,%7},{%8,%9},{%0,%1,%2,%3};"               \
                 : "+f"(c[0]), "+f"(c[1]), "+f"(c[2]), "+f"(c[3])                   \
                 : "r"(a0), "r"(a1), "r"(a2), "r"(a3), "r"(b0), "r"(b1))

#define SPITCH 136
#define ARRU32 (8 * SPITCH)
#define BUFU32 (4 * ARRU32)
#define GEMM_SMEM ((2 * BUFU32 + 128) * 4)

// OUT_SPLIT=1: emit bf16 hi/lo (Ch/Cl). OUT_SPLIT=0: emit fp16 (Cf).
template <int OUT_SPLIT>
__global__ void __launch_bounds__(256, 2)
k_gemm(const __nv_bfloat16* __restrict__ Ah_g, const __nv_bfloat16* __restrict__ Al_g,
       const __nv_bfloat16* __restrict__ Bh_g, const __nv_bfloat16* __restrict__ Bl_g,
       const float* __restrict__ bias, __half* __restrict__ Cf,
       __nv_bfloat16* __restrict__ Ch, __nv_bfloat16* __restrict__ Cl,
       int M, int N, int K) {
    extern __shared__ uint32_t sm[];
    float* bias_s = (float*)(sm + 2 * BUFU32);

    int tid = threadIdx.x;
    int lane = tid & 31;
    int wid = tid >> 5;
    int warp_m = wid & 1;
    int warp_n = wid >> 1;
    int gr = lane >> 2;
    int gc = lane & 3;

    int bm = blockIdx.y * 128;
    int bn = blockIdx.x * 128;

    if (tid < 128) bias_s[tid] = bias[bn + tid];

    float acc[4][4][4];
    #pragma unroll
    for (int i = 0; i < 4; i++)
        #pragma unroll
        for (int j = 0; j < 4; j++)
            #pragma unroll
            for (int q = 0; q < 4; q++) acc[i][j][q] = 0.f;

    const int mb = warp_m * 64;
    const int nb = warp_n * 32;
    const int r    = tid >> 1;
    const int half = tid & 1;
    const int kb2  = half * 4;

    const __nv_bfloat16* pAh = Ah_g + (size_t)(bm + r) * K + half * 8;
    const __nv_bfloat16* pAl = Al_g + (size_t)(bm + r) * K + half * 8;
    const __nv_bfloat16* pBh = Bh_g + (size_t)(bn + r) * K + half * 8;
    const __nv_bfloat16* pBl = Bl_g + (size_t)(bn + r) * K + half * 8;

    uint4 rAh, rAl, rBh, rBl;

#define LDG_CHUNK(k0)                                                   \
    do {                                                                \
        rAh = *(const uint4*)(pAh + (k0));                              \
        rAl = *(const uint4*)(pAl + (k0));                              \
        rBh = *(const uint4*)(pBh + (k0));                              \
        rBl = *(const uint4*)(pBl + (k0));                              \
    } while (0)

#define STS_CHUNK(buf)                                                  \
    do {                                                                \
        uint32_t* b0 = sm + (buf) * BUFU32;                             \
        uint32_t* b1 = b0 + ARRU32;                                     \
        uint32_t* b2 = b0 + 2 * ARRU32;                                 \
        uint32_t* b3 = b0 + 3 * ARRU32;                                 \
        b0[(kb2 + 0) * SPITCH + r] = rAh.x;                             \
        b0[(kb2 + 1) * SPITCH + r] = rAh.y;                             \
        b0[(kb2 + 2) * SPITCH + r] = rAh.z;                             \
        b0[(kb2 + 3) * SPITCH + r] = rAh.w;                             \
        b1[(kb2 + 0) * SPITCH + r] = rAl.x;                             \
        b1[(kb2 + 1) * SPITCH + r] = rAl.y;                             \
        b1[(kb2 + 2) * SPITCH + r] = rAl.z;                             \
        b1[(kb2 + 3) * SPITCH + r] = rAl.w;                             \
        b2[(kb2 + 0) * SPITCH + r] = rBh.x;                             \
        b2[(kb2 + 1) * SPITCH + r] = rBh.y;                             \
        b2[(kb2 + 2) * SPITCH + r] = rBh.z;                             \
        b2[(kb2 + 3) * SPITCH + r] = rBh.w;                             \
        b3[(kb2 + 0) * SPITCH + r] = rBl.x;                             \
        b3[(kb2 + 1) * SPITCH + r] = rBl.y;                             \
        b3[(kb2 + 2) * SPITCH + r] = rBl.z;                             \
        b3[(kb2 + 3) * SPITCH + r] = rBl.w;                             \
    } while (0)

    const int NC = K / 16;
    LDG_CHUNK(0);
    STS_CHUNK(0);
    __syncthreads();

    for (int c = 0; c < NC; c++) {
        if (c + 1 < NC) LDG_CHUNK((c + 1) * 16);

        const uint32_t* bAh = sm + (c & 1) * BUFU32;
        const uint32_t* bAl = bAh + ARRU32;
        const uint32_t* bBh = bAh + 2 * ARRU32;
        const uint32_t* bBl = bAh + 3 * ARRU32;

        uint32_t Bhf[4][2], Blf[4][2];
        #pragma unroll
        for (int nt = 0; nt < 4; nt++) {
            int n0 = nb + nt * 8 + gr;
            Bhf[nt][0] = bBh[gc * SPITCH + n0];
            Bhf[nt][1] = bBh[(gc + 4) * SPITCH + n0];
            Blf[nt][0] = bBl[gc * SPITCH + n0];
            Blf[nt][1] = bBl[(gc + 4) * SPITCH + n0];
        }
        #pragma unroll
        for (int mt = 0; mt < 4; mt++) {
            int m0 = mb + mt * 16 + gr;
            uint32_t Ahf[4], Alf[4];
            Ahf[0] = bAh[gc * SPITCH + m0];
            Ahf[1] = bAh[gc * SPITCH + m0 + 8];
            Ahf[2] = bAh[(gc + 4) * SPITCH + m0];
            Ahf[3] = bAh[(gc + 4) * SPITCH + m0 + 8];
            Alf[0] = bAl[gc * SPITCH + m0];
            Alf[1] = bAl[gc * SPITCH + m0 + 8];
            Alf[2] = bAl[(gc + 4) * SPITCH + m0];
            Alf[3] = bAl[(gc + 4) * SPITCH + m0 + 8];
            #pragma unroll
            for (int nt = 0; nt < 4; nt++) {
                MMA_BF16(acc[mt][nt], Ahf[0], Ahf[1], Ahf[2], Ahf[3],
                         Bhf[nt][0], Bhf[nt][1]);
                MMA_BF16(acc[mt][nt], Ahf[0], Ahf[1], Ahf[2], Ahf[3],
                         Blf[nt][0], Blf[nt][1]);
                MMA_BF16(acc[mt][nt], Alf[0], Alf[1], Alf[2], Alf[3],
                         Bhf[nt][0], Bhf[nt][1]);
            }
        }
        if (c + 1 < NC) STS_CHUNK((c + 1) & 1);
        __syncthreads();
    }

    // ---- epilogue ----
    #pragma unroll
    for (int nt = 0; nt < 4; nt++) {
        int nc = nb + nt * 8 + gc * 2;
        float2 bv = make_float2(bias_s[nc], bias_s[nc + 1]);
        int n0 = bn + nc;
        #pragma unroll
        for (int mt = 0; mt < 4; mt++) {
            int m0 = bm + mb + mt * 16 + gr;
            float v00 = tanhf(acc[mt][nt][0] + bv.x);
            float v01 = tanhf(acc[mt][nt][1] + bv.y);
            float v10 = tanhf(acc[mt][nt][2] + bv.x);
            float v11 = tanhf(acc[mt][nt][3] + bv.y);
            if (OUT_SPLIT) {
                __nv_bfloat16 h00 = __float2bfloat16_rn(v00);
                __nv_bfloat16 h01 = __float2bfloat16_rn(v01);
                __nv_bfloat16 h10 = __float2bfloat16_rn(v10);
                __nv_bfloat16 h11 = __float2bfloat16_rn(v11);
                *(__nv_bfloat162*)&Ch[(size_t)m0 * N + n0] = __nv_bfloat162(h00, h01);
                *(__nv_bfloat162*)&Ch[(size_t)(m0 + 8) * N + n0] = __nv_bfloat162(h10, h11);
                *(__nv_bfloat162*)&Cl[(size_t)m0 * N + n0] = __nv_bfloat162(
                    __float2bfloat16_rn(v00 - __bfloat162float(h00)),
                    __float2bfloat16_rn(v01 - __bfloat162float(h01)));
                *(__nv_bfloat162*)&Cl[(size_t)(m0 + 8) * N + n0] = __nv_bfloat162(
                    __float2bfloat16_rn(v10 - __bfloat162float(h10)),
                    __float2bfloat16_rn(v11 - __bfloat162float(h11)));
            } else {
                *(__half2*)&Cf[(size_t)m0 * N + n0] = __floats2half2_rn(v00, v01);
                *(__half2*)&Cf[(size_t)(m0 + 8) * N + n0] = __floats2half2_rn(v10, v11);
            }
        }
    }
}

// ================= decoder: fp16 gathers, fp32 accum, fused final =================
__global__ void k_decode(const int* __restrict__ tuser, const int* __restrict__ titem,
                         const float* __restrict__ trating,
                         const float* __restrict__ bdec, float* __restrict__ out,
                         int nt, int write_loss) {
    int warp = threadIdx.x >> 5, lane = threadIdx.x & 31;
    int base = blockIdx.x * 32 + warp * 4;
    double mine = 0.0;
    #pragma unroll
    for (int p = 0; p < 2; p++) {
        int t0 = base + p * 2;
        int t1 = t0 + 1;
        bool v0 = t0 < nt, v1 = t1 < nt;
        float s0 = 0.f, s1 = 0.f;
        int u0 = 0, i0 = 0, u1 = 0, i1 = 0;
        if (v0) { u0 = tuser[t0]; i0 = titem[t0]; }
        if (v1) { u1 = tuser[t1]; i1 = titem[t1]; }
        const uint4* ga = (const uint4*)(g_dec + (size_t)u0 * 512);  // 64 uint4/row
        const uint4* wa = (const uint4*)(g_wdh + (size_t)i0 * 512);
        const uint4* gb = (const uint4*)(g_dec + (size_t)u1 * 512);
        const uint4* wb = (const uint4*)(g_wdh + (size_t)i1 * 512);
        #pragma unroll
        for (int q = 0; q < 2; q++) {
            if (v0) {
                uint4 a = ga[q * 32 + lane];
                uint4 b = wa[q * 32 + lane];
                float2 f;
                f = __half22float2(*(__half2*)&a.x);
                float2 g = __half22float2(*(__half2*)&b.x);
                s0 = fmaf(f.x, g.x, s0); s0 = fmaf(f.y, g.y, s0);
                f = __half22float2(*(__half2*)&a.y); g = __half22float2(*(__half2*)&b.y);
                s0 = fmaf(f.x, g.x, s0); s0 = fmaf(f.y, g.y, s0);
                f = __half22float2(*(__half2*)&a.z); g = __half22float2(*(__half2*)&b.z);
                s0 = fmaf(f.x, g.x, s0); s0 = fmaf(f.y, g.y, s0);
                f = __half22float2(*(__half2*)&a.w); g = __half22float2(*(__half2*)&b.w);
                s0 = fmaf(f.x, g.x, s0); s0 = fmaf(f.y, g.y, s0);
            }
            if (v1) {
                uint4 a = gb[q * 32 + lane];
                uint4 b = wb[q * 32 + lane];
                float2 f, g;
                f = __half22float2(*(__half2*)&a.x); g = __half22float2(*(__half2*)&b.x);
                s1 = fmaf(f.x, g.x, s1); s1 = fmaf(f.y, g.y, s1);
                f = __half22float2(*(__half2*)&a.y); g = __half22float2(*(__half2*)&b.y);
                s1 = fmaf(f.x, g.x, s1); s1 = fmaf(f.y, g.y, s1);
                f = __half22float2(*(__half2*)&a.z); g = __half22float2(*(__half2*)&b.z);
                s1 = fmaf(f.x, g.x, s1); s1 = fmaf(f.y, g.y, s1);
                f = __half22float2(*(__half2*)&a.w); g = __half22float2(*(__half2*)&b.w);
                s1 = fmaf(f.x, g.x, s1); s1 = fmaf(f.y, g.y, s1);
            }
        }
        #pragma unroll
        for (int o = 16; o; o >>= 1) {
            s0 += __shfl_xor_sync(0xffffffffu, s0, o);
            s1 += __shfl_xor_sync(0xffffffffu, s1, o);
        }
        if (lane == 0) {
            if (v0) {
                float pred = s0 + bdec[i0];
                out[t0] = pred;
                float d = pred - trating[t0];
                mine += (double)d * (double)d;
            }
            if (v1) {
                float pred = s1 + bdec[i1];
                out[t1] = pred;
                float d = pred - trating[t1];
                mine += (double)d * (double)d;
            }
        }
    }
    __shared__ double part_s[8];
    __shared__ int is_last;
    if (lane == 0) part_s[warp] = mine;
    __syncthreads();
    if (threadIdx.x == 0) {
        double ss = 0.0;
        #pragma unroll
        for (int i = 0; i < 8; i++) ss += part_s[i];
        g_part[blockIdx.x] = ss;
        __threadfence();
        int done = atomicAdd(&g_dcount, 1);
        is_last = (done == (int)gridDim.x - 1);
        if (is_last) g_dcount = 0;
    }
    __syncthreads();
    if (is_last) {
        int nb = (int)gridDim.x;
        double s = 0.0;
        for (int i = threadIdx.x; i < nb; i += 256) s += g_part[i];
        __shared__ double red[8];
        #pragma unroll
        for (int o = 16; o; o >>= 1) s += __shfl_xor_sync(0xffffffffu, s, o);
        if (lane == 0) red[warp] = s;
        __syncthreads();
        if (threadIdx.x == 0) {
            double tot = 0.0;
            #pragma unroll
            for (int i = 0; i < 8; i++) tot += red[i];
            if (write_loss) out[nt] = (float)(tot / (double)nt);
        }
    }
}

// ================= launch =================
extern "C" void kernel_launch(void* const* d_in, const int* in_sizes, int n_in,
                              void* d_out, int out_size) {
    const int*   user    = (const int*)d_in[0];
    const int*   item    = (const int*)d_in[1];
    const float* rating  = (const float*)d_in[2];
    const int*   tuser   = (const int*)d_in[3];
    const int*   titem   = (const int*)d_in[4];
    const float* trating = (const float*)d_in[5];
    const float* W_enc   = (const float*)d_in[6];
    const float* b_enc   = (const float*)d_in[7];
    const float* W1      = (const float*)d_in[8];
    const float* b1      = (const float*)d_in[9];
    const float* W2      = (const float*)d_in[10];
    const float* b2      = (const float*)d_in[11];
    const float* W_dec   = (const float*)d_in[12];
    const float* b_dec   = (const float*)d_in[13];
    float* out = (float*)d_out;

    int N  = in_sizes[0];
    int NT = in_sizes[3];
    (void)n_in;

    void *cnt_ptr, *xh_p, *xl_p, *ench_p, *encl_p, *w1h_p, *w1l_p, *w2h_p, *w2l_p, *dec_p;
    cudaGetSymbolAddress(&cnt_ptr, g_cnt);
    cudaGetSymbolAddress(&xh_p, g_xh);
    cudaGetSymbolAddress(&xl_p, g_xl);
    cudaGetSymbolAddress(&ench_p, g_ench);
    cudaGetSymbolAddress(&encl_p, g_encl);
    cudaGetSymbolAddress(&w1h_p, g_w1h);
    cudaGetSymbolAddress(&w1l_p, g_w1l);
    cudaGetSymbolAddress(&w2h_p, g_w2h);
    cudaGetSymbolAddress(&w2l_p, g_w2l);
    cudaGetSymbolAddress(&dec_p, g_dec);

    cudaFuncSetAttribute(k_gemm<0>, cudaFuncAttributeMaxDynamicSharedMemorySize, GEMM_SMEM);
    cudaFuncSetAttribute(k_gemm<1>, cudaFuncAttributeMaxDynamicSharedMemorySize, GEMM_SMEM);

    // 0: zero counters
    cudaMemsetAsync(cnt_ptr, 0, NUM_USERS * sizeof(int), 0);
    // 1: transpose W_enc (fp16) + split W1/W2 + Wdec->fp16
    {
        dim3 g((NUM_ITEMS + 31) / 32, 33);   // y: 0-15 transpose, 16 splits, 17-32 Wdec
        k_prep<<<g, 256>>>(W_enc, W1, W2, W_dec);
    }
    // 2-4: counting sort by user
    k_hist<<<(N + 255) / 256, 256>>>(user, N);
    k_scan<<<1, 1024>>>(N);
    k_scatter<<<(N + 255) / 256, 256>>>(user, item, rating, N);
    // 5: encoder aggregation + tanh -> bf16 hi/lo
    k_encode<<<NUM_USERS, 128>>>(b_enc);
    // 6-7: MLP GEMMs
    {
        dim3 g1(LAT / 128, NUM_USERS / 128);
        k_gemm<1><<<g1, 256, GEMM_SMEM>>>(
            (const __nv_bfloat16*)xh_p, (const __nv_bfloat16*)xl_p,
            (const __nv_bfloat16*)w1h_p, (const __nv_bfloat16*)w1l_p,
            b1, nullptr, (__nv_bfloat16*)ench_p, (__nv_bfloat16*)encl_p,
            NUM_USERS, LAT, H0);
        dim3 g2(H0 / 128, NUM_USERS / 128);
        k_gemm<0><<<g2, 256, GEMM_SMEM>>>(
            (const __nv_bfloat16*)ench_p, (const __nv_bfloat16*)encl_p,
            (const __nv_bfloat16*)w2h_p, (const __nv_bfloat16*)w2l_p,
            b2, (__half*)dec_p, nullptr, nullptr,
            NUM_USERS, H0, LAT);
    }
    // 8: decoder + loss
    k_decode<<<(NT + 31) / 32, 256>>>(tuser, titem, trating, b_dec, out, NT,
                                      out_size > NT ? 1 : 0);
}

// round 8
// speedup vs baseline: 1.8203x; 1.2213x over previous
#include <cuda_runtime.h>
#include <cuda_bf16.h>
#include <cuda_fp16.h>
#include <math.h>
#include <stdint.h>

// ---- fixed problem shape ----
#define NUM_ITEMS 50000
#define NUM_USERS 16384
#define H0 512
#define LAT 256
#define NMAX 262144

// ---- scratch ----
static __device__ __half g_WencT[(size_t)NUM_ITEMS * H0];    // fp16 [items, H0]
static __device__ __half g_wdh[(size_t)NUM_ITEMS * H0];      // fp16 Wdec [items, H0]
static __device__ __half g_x[(size_t)NUM_USERS * H0];        // fp16 encoder input
static __device__ __half g_enc[(size_t)NUM_USERS * LAT];     // fp16 latent
static __device__ __half g_w1[(size_t)LAT * H0];             // fp16 W1
static __device__ __half g_w2[(size_t)H0 * LAT];             // fp16 W2
static __device__ __half g_dec[(size_t)NUM_USERS * H0];      // fp16 decoded
static __device__ int    g_cnt[NUM_USERS];
static __device__ int    g_off[NUM_USERS + 1];
static __device__ int    g_cur[NUM_USERS];
static __device__ int    g_pitem[NMAX];
static __device__ float  g_prate[NMAX];
static __device__ double g_part[NMAX / 32];
static __device__ int    g_dcount;

// ================= prep: transpose W_enc (fp16) + W1/W2->fp16 + Wdec->fp16 =================
__global__ void k_prep(const float* __restrict__ W, const float* __restrict__ W1,
                       const float* __restrict__ W2, const float* __restrict__ Wdec) {
    int by = blockIdx.y;
    if (by < 16) {
        // transpose W_enc [H0, NUM_ITEMS] -> g_WencT [NUM_ITEMS, H0] (fp16)
        __shared__ float tile[32][33];
        int t = threadIdx.x;
        int tx = t & 31, ty = t >> 5;                      // (32, 8)
        int col0 = blockIdx.x * 32;
        int row0 = by * 32;
        #pragma unroll
        for (int j = 0; j < 4; j++) {
            int r = ty + j * 8, c = col0 + tx;
            if (c < NUM_ITEMS) tile[r][tx] = W[(size_t)(row0 + r) * NUM_ITEMS + c];
        }
        __syncthreads();
        #pragma unroll
        for (int j = 0; j < 4; j++) {
            int i = col0 + ty + j * 8, h = row0 + tx;
            if (i < NUM_ITEMS)
                g_WencT[(size_t)i * H0 + h] = __float2half_rn(tile[tx][ty + j * 8]);
        }
    } else if (by == 16) {
        // W1 / W2 -> fp16
        int i = blockIdx.x * blockDim.x + threadIdx.x;     // float4 units
        const int n1 = LAT * H0 / 4;                       // 32768
        if (i >= 2 * n1) return;
        const float* src; __half* dst; int j;
        if (i < n1) { src = W1; dst = g_w1; j = i; }
        else        { src = W2; dst = g_w2; j = i - n1; }
        float4 v = ((const float4*)src)[j];
        ((__half2*)dst)[j * 2 + 0] = __floats2half2_rn(v.x, v.y);
        ((__half2*)dst)[j * 2 + 1] = __floats2half2_rn(v.z, v.w);
    } else {
        // Wdec fp32 -> fp16
        int idx = ((by - 17) * (int)gridDim.x + blockIdx.x) * 256 + threadIdx.x;
        if (idx >= NUM_ITEMS * H0 / 4) return;
        float4 v = ((const float4*)Wdec)[idx];
        ((__half2*)g_wdh)[idx * 2 + 0] = __floats2half2_rn(v.x, v.y);
        ((__half2*)g_wdh)[idx * 2 + 1] = __floats2half2_rn(v.z, v.w);
    }
}

// ================= counting sort =================
__global__ void k_hist(const int* __restrict__ user, int n) {
    int i = blockIdx.x * blockDim.x + threadIdx.x;
    if (i < n) atomicAdd(&g_cnt[user[i]], 1);
}

__global__ void k_scan(int n) {
    int t = threadIdx.x;
    int lane = t & 31, wid = t >> 5;
    int base = t * 16;
    int local[16];
    int s = 0;
    #pragma unroll
    for (int i = 0; i < 16; i++) { local[i] = g_cnt[base + i]; s += local[i]; }
    int v = s;
    #pragma unroll
    for (int o = 1; o < 32; o <<= 1) {
        int u = __shfl_up_sync(0xffffffffu, v, o);
        if (lane >= o) v += u;
    }
    __shared__ int wsum[32];
    if (lane == 31) wsum[wid] = v;
    __syncthreads();
    if (wid == 0) {
        int w = wsum[lane];
        #pragma unroll
        for (int o = 1; o < 32; o <<= 1) {
            int u = __shfl_up_sync(0xffffffffu, w, o);
            if (lane >= o) w += u;
        }
        wsum[lane] = w;
    }
    __syncthreads();
    int run = (wid ? wsum[wid - 1] : 0) + (v - s);
    #pragma unroll
    for (int i = 0; i < 16; i++) {
        g_off[base + i] = run;
        g_cur[base + i] = run;
        run += local[i];
    }
    if (t == 1023) g_off[NUM_USERS] = n;
}

__global__ void k_scatter(const int* __restrict__ user, const int* __restrict__ item,
                          const float* __restrict__ rating, int n) {
    int i = blockIdx.x * blockDim.x + threadIdx.x;
    if (i < n) {
        int p = atomicAdd(&g_cur[user[i]], 1);
        g_pitem[p] = item[i];
        g_prate[p] = rating[i];
    }
}

// ================= encoder aggregation (fp16 gathers, fp32 accum) -> fp16 x =================
__global__ void k_encode(const float* __restrict__ b_enc) {
    int u = blockIdx.x;
    int t = threadIdx.x;                                   // 128; each handles 4 h
    int s = g_off[u], e = g_off[u + 1];
    const uint2* WT = (const uint2*)g_WencT;               // 4 halves per uint2, 128 per row
    float4 acc0 = make_float4(0.f, 0.f, 0.f, 0.f);
    float4 acc1 = make_float4(0.f, 0.f, 0.f, 0.f);
    __shared__ int   sit[128];
    __shared__ float srt[128];
    for (int j0 = s; j0 < e; j0 += 128) {
        int c = min(128, e - j0);
        if (t < c) { sit[t] = g_pitem[j0 + t]; srt[t] = g_prate[j0 + t]; }
        __syncthreads();
        int q = 0;
        for (; q + 1 < c; q += 2) {
            int i0 = sit[q], i1 = sit[q + 1];
            float r0 = srt[q], r1 = srt[q + 1];
            uint2 w0 = WT[(size_t)i0 * 128 + t];
            uint2 w1 = WT[(size_t)i1 * 128 + t];
            float2 a = __half22float2(*(__half2*)&w0.x);
            float2 b = __half22float2(*(__half2*)&w0.y);
            float2 cc = __half22float2(*(__half2*)&w1.x);
            float2 d = __half22float2(*(__half2*)&w1.y);
            acc0.x = fmaf(r0, a.x, acc0.x); acc1.x = fmaf(r1, cc.x, acc1.x);
            acc0.y = fmaf(r0, a.y, acc0.y); acc1.y = fmaf(r1, cc.y, acc1.y);
            acc0.z = fmaf(r0, b.x, acc0.z); acc1.z = fmaf(r1, d.x, acc1.z);
            acc0.w = fmaf(r0, b.y, acc0.w); acc1.w = fmaf(r1, d.y, acc1.w);
        }
        if (q < c) {
            int i0 = sit[q]; float r0 = srt[q];
            uint2 w0 = WT[(size_t)i0 * 128 + t];
            float2 a = __half22float2(*(__half2*)&w0.x);
            float2 b = __half22float2(*(__half2*)&w0.y);
            acc0.x = fmaf(r0, a.x, acc0.x);
            acc0.y = fmaf(r0, a.y, acc0.y);
            acc0.z = fmaf(r0, b.x, acc0.z);
            acc0.w = fmaf(r0, b.y, acc0.w);
        }
        __syncthreads();
    }
    float4 b = ((const float4*)b_enc)[t];
    float vx = tanhf(acc0.x + acc1.x + b.x);
    float vy = tanhf(acc0.y + acc1.y + b.y);
    float vz = tanhf(acc0.z + acc1.z + b.z);
    float vw = tanhf(acc0.w + acc1.w + b.w);
    size_t o2 = (size_t)u * 256 + t * 2;
    ((__half2*)g_x)[o2 + 0] = __floats2half2_rn(vx, vy);
    ((__half2*)g_x)[o2 + 1] = __floats2half2_rn(vz, vw);
}

// ================= fp16 single-pass tensor-core GEMM =================
// C[M,N] = tanh(A[M,K] @ B[N,K]^T + bias[N]); fp16 in, fp32 accum, fp16 out.
// Block tile 128x128, k-chunk 32, 256 threads = 8 warps (2M x 4N), double buffered.

#define MMA_F16(c, a0, a1, a2, a3, b0, b1)                                          \
    asm volatile("mma.sync.aligned.m16n8k16.row.col.f32.f16.f16.f32 "               \
                 "{%0,%1,%2,%3},{%4,%5,%6,%7},{%8,%9},{%0,%1,%2,%3};"               \
                 : "+f"(c[0]), "+f"(c[1]), "+f"(c[2]), "+f"(c[3])                   \
                 : "r"(a0), "r"(a1), "r"(a2), "r"(a3), "r"(b0), "r"(b1))

#define SPITCH 136
#define ARRU32 (16 * SPITCH)        // one [k2][row] slab (k2 = 0..15)
#define BUFU32 (2 * ARRU32)         // A, B
#define GEMM_SMEM ((2 * BUFU32 + 128) * 4)

__global__ void __launch_bounds__(256, 2)
k_gemm(const __half* __restrict__ A, const __half* __restrict__ B,
       const float* __restrict__ bias, __half* __restrict__ C,
       int M, int N, int K) {
    extern __shared__ uint32_t sm[];
    float* bias_s = (float*)(sm + 2 * BUFU32);

    int tid = threadIdx.x;
    int lane = tid & 31;
    int wid = tid >> 5;
    int warp_m = wid & 1;
    int warp_n = wid >> 1;
    int gr = lane >> 2;
    int gc = lane & 3;

    int bm = blockIdx.y * 128;
    int bn = blockIdx.x * 128;

    if (tid < 128) bias_s[tid] = bias[bn + tid];

    float acc[4][4][4];
    #pragma unroll
    for (int i = 0; i < 4; i++)
        #pragma unroll
        for (int j = 0; j < 4; j++)
            #pragma unroll
            for (int q = 0; q < 4; q++) acc[i][j][q] = 0.f;

    const int mb = warp_m * 64;
    const int nb = warp_n * 32;
    const int r    = tid >> 1;       // row within tile
    const int half = tid & 1;        // which 16-wide k half of the 32 chunk
    const int kb2  = half * 8;       // k2 base for STS

    const __half* pA = A + (size_t)(bm + r) * K + half * 16;
    const __half* pB = B + (size_t)(bn + r) * K + half * 16;

    uint4 rA0, rA1, rB0, rB1;

#define LDG_CHUNK(k0)                                                   \
    do {                                                                \
        rA0 = *(const uint4*)(pA + (k0));                               \
        rA1 = *(const uint4*)(pA + (k0) + 8);                           \
        rB0 = *(const uint4*)(pB + (k0));                               \
        rB1 = *(const uint4*)(pB + (k0) + 8);                           \
    } while (0)

#define STS_CHUNK(buf)                                                  \
    do {                                                                \
        uint32_t* bA = sm + (buf) * BUFU32;                             \
        uint32_t* bB = bA + ARRU32;                                     \
        bA[(kb2 + 0) * SPITCH + r] = rA0.x;                             \
        bA[(kb2 + 1) * SPITCH + r] = rA0.y;                             \
        bA[(kb2 + 2) * SPITCH + r] = rA0.z;                             \
        bA[(kb2 + 3) * SPITCH + r] = rA0.w;                             \
        bA[(kb2 + 4) * SPITCH + r] = rA1.x;                             \
        bA[(kb2 + 5) * SPITCH + r] = rA1.y;                             \
        bA[(kb2 + 6) * SPITCH + r] = rA1.z;                             \
        bA[(kb2 + 7) * SPITCH + r] = rA1.w;                             \
        bB[(kb2 + 0) * SPITCH + r] = rB0.x;                             \
        bB[(kb2 + 1) * SPITCH + r] = rB0.y;                             \
        bB[(kb2 + 2) * SPITCH + r] = rB0.z;                             \
        bB[(kb2 + 3) * SPITCH + r] = rB0.w;                             \
        bB[(kb2 + 4) * SPITCH + r] = rB1.x;                             \
        bB[(kb2 + 5) * SPITCH + r] = rB1.y;                             \
        bB[(kb2 + 6) * SPITCH + r] = rB1.z;                             \
        bB[(kb2 + 7) * SPITCH + r] = rB1.w;                             \
    } while (0)

    const int NC = K / 32;
    LDG_CHUNK(0);
    STS_CHUNK(0);
    __syncthreads();

    for (int c = 0; c < NC; c++) {
        if (c + 1 < NC) LDG_CHUNK((c + 1) * 32);

        const uint32_t* bA = sm + (c & 1) * BUFU32;
        const uint32_t* bB = bA + ARRU32;

        #pragma unroll
        for (int ks = 0; ks < 2; ks++) {
            int kb = ks * 8;
            uint32_t Bf[4][2];
            #pragma unroll
            for (int nt = 0; nt < 4; nt++) {
                int n0 = nb + nt * 8 + gr;
                Bf[nt][0] = bB[(kb + gc) * SPITCH + n0];
                Bf[nt][1] = bB[(kb + gc + 4) * SPITCH + n0];
            }
            #pragma unroll
            for (int mt = 0; mt < 4; mt++) {
                int m0 = mb + mt * 16 + gr;
                uint32_t Af[4];
                Af[0] = bA[(kb + gc) * SPITCH + m0];
                Af[1] = bA[(kb + gc) * SPITCH + m0 + 8];
                Af[2] = bA[(kb + gc + 4) * SPITCH + m0];
                Af[3] = bA[(kb + gc + 4) * SPITCH + m0 + 8];
                #pragma unroll
                for (int nt = 0; nt < 4; nt++)
                    MMA_F16(acc[mt][nt], Af[0], Af[1], Af[2], Af[3],
                            Bf[nt][0], Bf[nt][1]);
            }
        }
        if (c + 1 < NC) STS_CHUNK((c + 1) & 1);
        __syncthreads();
    }

    // ---- epilogue: bias + tanh -> fp16 ----
    #pragma unroll
    for (int nt = 0; nt < 4; nt++) {
        int nc = nb + nt * 8 + gc * 2;
        float2 bv = make_float2(bias_s[nc], bias_s[nc + 1]);
        int n0 = bn + nc;
        #pragma unroll
        for (int mt = 0; mt < 4; mt++) {
            int m0 = bm + mb + mt * 16 + gr;
            float v00 = tanhf(acc[mt][nt][0] + bv.x);
            float v01 = tanhf(acc[mt][nt][1] + bv.y);
            float v10 = tanhf(acc[mt][nt][2] + bv.x);
            float v11 = tanhf(acc[mt][nt][3] + bv.y);
            *(__half2*)&C[(size_t)m0 * N + n0] = __floats2half2_rn(v00, v01);
            *(__half2*)&C[(size_t)(m0 + 8) * N + n0] = __floats2half2_rn(v10, v11);
        }
    }
}

// ================= decoder: fp16 gathers, fp32 accum, fused final =================
__global__ void k_decode(const int* __restrict__ tuser, const int* __restrict__ titem,
                         const float* __restrict__ trating,
                         const float* __restrict__ bdec, float* __restrict__ out,
                         int nt, int write_loss) {
    int warp = threadIdx.x >> 5, lane = threadIdx.x & 31;
    int base = blockIdx.x * 32 + warp * 4;
    double mine = 0.0;
    #pragma unroll
    for (int p = 0; p < 2; p++) {
        int t0 = base + p * 2;
        int t1 = t0 + 1;
        bool v0 = t0 < nt, v1 = t1 < nt;
        float s0 = 0.f, s1 = 0.f;
        int u0 = 0, i0 = 0, u1 = 0, i1 = 0;
        if (v0) { u0 = tuser[t0]; i0 = titem[t0]; }
        if (v1) { u1 = tuser[t1]; i1 = titem[t1]; }
        const uint4* ga = (const uint4*)(g_dec + (size_t)u0 * 512);
        const uint4* wa = (const uint4*)(g_wdh + (size_t)i0 * 512);
        const uint4* gb = (const uint4*)(g_dec + (size_t)u1 * 512);
        const uint4* wb = (const uint4*)(g_wdh + (size_t)i1 * 512);
        #pragma unroll
        for (int q = 0; q < 2; q++) {
            if (v0) {
                uint4 a = ga[q * 32 + lane];
                uint4 b = wa[q * 32 + lane];
                float2 f, g;
                f = __half22float2(*(__half2*)&a.x); g = __half22float2(*(__half2*)&b.x);
                s0 = fmaf(f.x, g.x, s0); s0 = fmaf(f.y, g.y, s0);
                f = __half22float2(*(__half2*)&a.y); g = __half22float2(*(__half2*)&b.y);
                s0 = fmaf(f.x, g.x, s0); s0 = fmaf(f.y, g.y, s0);
                f = __half22float2(*(__half2*)&a.z); g = __half22float2(*(__half2*)&b.z);
                s0 = fmaf(f.x, g.x, s0); s0 = fmaf(f.y, g.y, s0);
                f = __half22float2(*(__half2*)&a.w); g = __half22float2(*(__half2*)&b.w);
                s0 = fmaf(f.x, g.x, s0); s0 = fmaf(f.y, g.y, s0);
            }
            if (v1) {
                uint4 a = gb[q * 32 + lane];
                uint4 b = wb[q * 32 + lane];
                float2 f, g;
                f = __half22float2(*(__half2*)&a.x); g = __half22float2(*(__half2*)&b.x);
                s1 = fmaf(f.x, g.x, s1); s1 = fmaf(f.y, g.y, s1);
                f = __half22float2(*(__half2*)&a.y); g = __half22float2(*(__half2*)&b.y);
                s1 = fmaf(f.x, g.x, s1); s1 = fmaf(f.y, g.y, s1);
                f = __half22float2(*(__half2*)&a.z); g = __half22float2(*(__half2*)&b.z);
                s1 = fmaf(f.x, g.x, s1); s1 = fmaf(f.y, g.y, s1);
                f = __half22float2(*(__half2*)&a.w); g = __half22float2(*(__half2*)&b.w);
                s1 = fmaf(f.x, g.x, s1); s1 = fmaf(f.y, g.y, s1);
            }
        }
        #pragma unroll
        for (int o = 16; o; o >>= 1) {
            s0 += __shfl_xor_sync(0xffffffffu, s0, o);
            s1 += __shfl_xor_sync(0xffffffffu, s1, o);
        }
        if (lane == 0) {
            if (v0) {
                float pred = s0 + bdec[i0];
                out[t0] = pred;
                float d = pred - trating[t0];
                mine += (double)d * (double)d;
            }
            if (v1) {
                float pred = s1 + bdec[i1];
                out[t1] = pred;
                float d = pred - trating[t1];
                mine += (double)d * (double)d;
            }
        }
    }
    __shared__ double part_s[8];
    __shared__ int is_last;
    if (lane == 0) part_s[warp] = mine;
    __syncthreads();
    if (threadIdx.x == 0) {
        double ss = 0.0;
        #pragma unroll
        for (int i = 0; i < 8; i++) ss += part_s[i];
        g_part[blockIdx.x] = ss;
        __threadfence();
        int done = atomicAdd(&g_dcount, 1);
        is_last = (done == (int)gridDim.x - 1);
        if (is_last) g_dcount = 0;
    }
    __syncthreads();
    if (is_last) {
        int nb = (int)gridDim.x;
        double s = 0.0;
        for (int i = threadIdx.x; i < nb; i += 256) s += g_part[i];
        __shared__ double red[8];
        #pragma unroll
        for (int o = 16; o; o >>= 1) s += __shfl_xor_sync(0xffffffffu, s, o);
        if (lane == 0) red[warp] = s;
        __syncthreads();
        if (threadIdx.x == 0) {
            double tot = 0.0;
            #pragma unroll
            for (int i = 0; i < 8; i++) tot += red[i];
            if (write_loss) out[nt] = (float)(tot / (double)nt);
        }
    }
}

// ================= launch =================
extern "C" void kernel_launch(void* const* d_in, const int* in_sizes, int n_in,
                              void* d_out, int out_size) {
    const int*   user    = (const int*)d_in[0];
    const int*   item    = (const int*)d_in[1];
    const float* rating  = (const float*)d_in[2];
    const int*   tuser   = (const int*)d_in[3];
    const int*   titem   = (const int*)d_in[4];
    const float* trating = (const float*)d_in[5];
    const float* W_enc   = (const float*)d_in[6];
    const float* b_enc   = (const float*)d_in[7];
    const float* W1      = (const float*)d_in[8];
    const float* b1      = (const float*)d_in[9];
    const float* W2      = (const float*)d_in[10];
    const float* b2      = (const float*)d_in[11];
    const float* W_dec   = (const float*)d_in[12];
    const float* b_dec   = (const float*)d_in[13];
    float* out = (float*)d_out;

    int N  = in_sizes[0];
    int NT = in_sizes[3];
    (void)n_in;

    void *cnt_ptr, *x_p, *enc_p, *w1_p, *w2_p, *dec_p;
    cudaGetSymbolAddress(&cnt_ptr, g_cnt);
    cudaGetSymbolAddress(&x_p, g_x);
    cudaGetSymbolAddress(&enc_p, g_enc);
    cudaGetSymbolAddress(&w1_p, g_w1);
    cudaGetSymbolAddress(&w2_p, g_w2);
    cudaGetSymbolAddress(&dec_p, g_dec);

    cudaFuncSetAttribute(k_gemm, cudaFuncAttributeMaxDynamicSharedMemorySize, GEMM_SMEM);

    // 0: zero counters
    cudaMemsetAsync(cnt_ptr, 0, NUM_USERS * sizeof(int), 0);
    // 1: transpose W_enc (fp16) + W1/W2->fp16 + Wdec->fp16
    {
        dim3 g((NUM_ITEMS + 31) / 32, 33);   // y: 0-15 transpose, 16 W1/W2, 17-32 Wdec
        k_prep<<<g, 256>>>(W_enc, W1, W2, W_dec);
    }
    // 2-4: counting sort by user
    k_hist<<<(N + 255) / 256, 256>>>(user, N);
    k_scan<<<1, 1024>>>(N);
    k_scatter<<<(N + 255) / 256, 256>>>(user, item, rating, N);
    // 5: encoder aggregation + tanh -> fp16 x
    k_encode<<<NUM_USERS, 128>>>(b_enc);
    // 6-7: MLP GEMMs (fp16 single-pass)
    {
        dim3 g1(LAT / 128, NUM_USERS / 128);
        k_gemm<<<g1, 256, GEMM_SMEM>>>((const __half*)x_p, (const __half*)w1_p,
                                       b1, (__half*)enc_p, NUM_USERS, LAT, H0);
        dim3 g2(H0 / 128, NUM_USERS / 128);
        k_gemm<<<g2, 256, GEMM_SMEM>>>((const __half*)enc_p, (const __half*)w2_p,
                                       b2, (__half*)dec_p, NUM_USERS, H0, LAT);
    }
    // 8: decoder + loss
    k_decode<<<(NT + 31) / 32, 256>>>(tuser, titem, trating, b_dec, out, NT,
                                      out_size > NT ? 1 : 0);
}

// round 9
// speedup vs baseline: 2.0201x; 1.1097x over previous
#include <cuda_runtime.h>
#include <cuda_bf16.h>
#include <cuda_fp16.h>
#include <math.h>
#include <stdint.h>

// ---- fixed problem shape ----
#define NUM_ITEMS 50000
#define NUM_USERS 16384
#define H0 512
#define LAT 256
#define NMAX 262144

// ---- scratch ----
static __device__ __half g_WencT[(size_t)NUM_ITEMS * H0];    // fp16 [items, H0]
static __device__ __half g_wdh[(size_t)NUM_ITEMS * H0];      // fp16 Wdec [items, H0]
static __device__ __half g_x[(size_t)NUM_USERS * H0];        // fp16 encoder input
static __device__ __half g_enc[(size_t)NUM_USERS * LAT];     // fp16 latent
static __device__ __half g_w1[(size_t)LAT * H0];             // fp16 W1
static __device__ __half g_w2[(size_t)H0 * LAT];             // fp16 W2
static __device__ __half g_dec[(size_t)NUM_USERS * H0];      // fp16 decoded
static __device__ int    g_cnt[NUM_USERS];
static __device__ int    g_off[NUM_USERS + 1];
static __device__ int    g_cur[NUM_USERS];
static __device__ int    g_pitem[NMAX];
static __device__ float  g_prate[NMAX];
static __device__ double g_part[NMAX / 32];
static __device__ int    g_dcount;

// ================= prep (main): transpose W_enc (fp16) + W1/W2->fp16 =================
__global__ void k_prep_main(const float* __restrict__ W, const float* __restrict__ W1,
                            const float* __restrict__ W2) {
    int by = blockIdx.y;
    if (by < 16) {
        // transpose W_enc [H0, NUM_ITEMS] -> g_WencT [NUM_ITEMS, H0] (fp16)
        __shared__ float tile[32][33];
        int t = threadIdx.x;
        int tx = t & 31, ty = t >> 5;                      // (32, 8)
        int col0 = blockIdx.x * 32;
        int row0 = by * 32;
        #pragma unroll
        for (int j = 0; j < 4; j++) {
            int r = ty + j * 8, c = col0 + tx;
            if (c < NUM_ITEMS) tile[r][tx] = W[(size_t)(row0 + r) * NUM_ITEMS + c];
        }
        __syncthreads();
        #pragma unroll
        for (int j = 0; j < 4; j++) {
            int i = col0 + ty + j * 8, h = row0 + tx;
            if (i < NUM_ITEMS)
                g_WencT[(size_t)i * H0 + h] = __float2half_rn(tile[tx][ty + j * 8]);
        }
    } else {
        // W1 / W2 -> fp16
        int i = blockIdx.x * blockDim.x + threadIdx.x;     // float4 units
        const int n1 = LAT * H0 / 4;                       // 32768
        if (i >= 2 * n1) return;
        const float* src; __half* dst; int j;
        if (i < n1) { src = W1; dst = g_w1; j = i; }
        else        { src = W2; dst = g_w2; j = i - n1; }
        float4 v = ((const float4*)src)[j];
        ((__half2*)dst)[j * 2 + 0] = __floats2half2_rn(v.x, v.y);
        ((__half2*)dst)[j * 2 + 1] = __floats2half2_rn(v.z, v.w);
    }
}

// ================= prep (side): Wdec -> fp16 =================
__global__ void k_prep_wdec(const float* __restrict__ Wdec) {
    int idx = blockIdx.x * blockDim.x + threadIdx.x;       // float4 units
    if (idx >= NUM_ITEMS * H0 / 4) return;
    float4 v = ((const float4*)Wdec)[idx];
    ((__half2*)g_wdh)[idx * 2 + 0] = __floats2half2_rn(v.x, v.y);
    ((__half2*)g_wdh)[idx * 2 + 1] = __floats2half2_rn(v.z, v.w);
}

// ================= counting sort =================
__global__ void k_hist(const int* __restrict__ user, int n) {
    int i = blockIdx.x * blockDim.x + threadIdx.x;
    if (i < n) atomicAdd(&g_cnt[user[i]], 1);
}

__global__ void k_scan(int n) {
    int t = threadIdx.x;
    int lane = t & 31, wid = t >> 5;
    int base = t * 16;
    int local[16];
    int s = 0;
    #pragma unroll
    for (int i = 0; i < 16; i++) { local[i] = g_cnt[base + i]; s += local[i]; }
    int v = s;
    #pragma unroll
    for (int o = 1; o < 32; o <<= 1) {
        int u = __shfl_up_sync(0xffffffffu, v, o);
        if (lane >= o) v += u;
    }
    __shared__ int wsum[32];
    if (lane == 31) wsum[wid] = v;
    __syncthreads();
    if (wid == 0) {
        int w = wsum[lane];
        #pragma unroll
        for (int o = 1; o < 32; o <<= 1) {
            int u = __shfl_up_sync(0xffffffffu, w, o);
            if (lane >= o) w += u;
        }
        wsum[lane] = w;
    }
    __syncthreads();
    int run = (wid ? wsum[wid - 1] : 0) + (v - s);
    #pragma unroll
    for (int i = 0; i < 16; i++) {
        g_off[base + i] = run;
        g_cur[base + i] = run;
        run += local[i];
    }
    if (t == 1023) g_off[NUM_USERS] = n;
}

__global__ void k_scatter(const int* __restrict__ user, const int* __restrict__ item,
                          const float* __restrict__ rating, int n) {
    int i = blockIdx.x * blockDim.x + threadIdx.x;
    if (i < n) {
        int p = atomicAdd(&g_cur[user[i]], 1);
        g_pitem[p] = item[i];
        g_prate[p] = rating[i];
    }
}

// ================= encoder aggregation (fp16 gathers, fp32 accum) -> fp16 x =================
__global__ void k_encode(const float* __restrict__ b_enc) {
    int u = blockIdx.x;
    int t = threadIdx.x;                                   // 128; each handles 4 h
    int s = g_off[u], e = g_off[u + 1];
    const uint2* WT = (const uint2*)g_WencT;
    float4 acc0 = make_float4(0.f, 0.f, 0.f, 0.f);
    float4 acc1 = make_float4(0.f, 0.f, 0.f, 0.f);
    __shared__ int   sit[128];
    __shared__ float srt[128];
    for (int j0 = s; j0 < e; j0 += 128) {
        int c = min(128, e - j0);
        if (t < c) { sit[t] = g_pitem[j0 + t]; srt[t] = g_prate[j0 + t]; }
        __syncthreads();
        int q = 0;
        for (; q + 1 < c; q += 2) {
            int i0 = sit[q], i1 = sit[q + 1];
            float r0 = srt[q], r1 = srt[q + 1];
            uint2 w0 = WT[(size_t)i0 * 128 + t];
            uint2 w1 = WT[(size_t)i1 * 128 + t];
            float2 a = __half22float2(*(__half2*)&w0.x);
            float2 b = __half22float2(*(__half2*)&w0.y);
            float2 cc = __half22float2(*(__half2*)&w1.x);
            float2 d = __half22float2(*(__half2*)&w1.y);
            acc0.x = fmaf(r0, a.x, acc0.x); acc1.x = fmaf(r1, cc.x, acc1.x);
            acc0.y = fmaf(r0, a.y, acc0.y); acc1.y = fmaf(r1, cc.y, acc1.y);
            acc0.z = fmaf(r0, b.x, acc0.z); acc1.z = fmaf(r1, d.x, acc1.z);
            acc0.w = fmaf(r0, b.y, acc0.w); acc1.w = fmaf(r1, d.y, acc1.w);
        }
        if (q < c) {
            int i0 = sit[q]; float r0 = srt[q];
            uint2 w0 = WT[(size_t)i0 * 128 + t];
            float2 a = __half22float2(*(__half2*)&w0.x);
            float2 b = __half22float2(*(__half2*)&w0.y);
            acc0.x = fmaf(r0, a.x, acc0.x);
            acc0.y = fmaf(r0, a.y, acc0.y);
            acc0.z = fmaf(r0, b.x, acc0.z);
            acc0.w = fmaf(r0, b.y, acc0.w);
        }
        __syncthreads();
    }
    float4 b = ((const float4*)b_enc)[t];
    float vx = tanhf(acc0.x + acc1.x + b.x);
    float vy = tanhf(acc0.y + acc1.y + b.y);
    float vz = tanhf(acc0.z + acc1.z + b.z);
    float vw = tanhf(acc0.w + acc1.w + b.w);
    size_t o2 = (size_t)u * 256 + t * 2;
    ((__half2*)g_x)[o2 + 0] = __floats2half2_rn(vx, vy);
    ((__half2*)g_x)[o2 + 1] = __floats2half2_rn(vz, vw);
}

// ================= fp16 single-pass tensor-core GEMM =================
#define MMA_F16(c, a0, a1, a2, a3, b0, b1)                                          \
    asm volatile("mma.sync.aligned.m16n8k16.row.col.f32.f16.f16.f32 "               \
                 "{%0,%1,%2,%3},{%4,%5,%6,%7},{%8,%9},{%0,%1,%2,%3};"               \
                 : "+f"(c[0]), "+f"(c[1]), "+f"(c[2]), "+f"(c[3])                   \
                 : "r"(a0), "r"(a1), "r"(a2), "r"(a3), "r"(b0), "r"(b1))

#define SPITCH 136
#define ARRU32 (16 * SPITCH)
#define BUFU32 (2 * ARRU32)
#define GEMM_SMEM ((2 * BUFU32 + 128) * 4)

__global__ void __launch_bounds__(256, 2)
k_gemm(const __half* __restrict__ A, const __half* __restrict__ B,
       const float* __restrict__ bias, __half* __restrict__ C,
       int M, int N, int K) {
    extern __shared__ uint32_t sm[];
    float* bias_s = (float*)(sm + 2 * BUFU32);

    int tid = threadIdx.x;
    int lane = tid & 31;
    int wid = tid >> 5;
    int warp_m = wid & 1;
    int warp_n = wid >> 1;
    int gr = lane >> 2;
    int gc = lane & 3;

    int bm = blockIdx.y * 128;
    int bn = blockIdx.x * 128;

    if (tid < 128) bias_s[tid] = bias[bn + tid];

    float acc[4][4][4];
    #pragma unroll
    for (int i = 0; i < 4; i++)
        #pragma unroll
        for (int j = 0; j < 4; j++)
            #pragma unroll
            for (int q = 0; q < 4; q++) acc[i][j][q] = 0.f;

    const int mb = warp_m * 64;
    const int nb = warp_n * 32;
    const int r    = tid >> 1;
    const int half = tid & 1;
    const int kb2  = half * 8;

    const __half* pA = A + (size_t)(bm + r) * K + half * 16;
    const __half* pB = B + (size_t)(bn + r) * K + half * 16;

    uint4 rA0, rA1, rB0, rB1;

#define LDG_CHUNK(k0)                                                   \
    do {                                                                \
        rA0 = *(const uint4*)(pA + (k0));                               \
        rA1 = *(const uint4*)(pA + (k0) + 8);                           \
        rB0 = *(const uint4*)(pB + (k0));                               \
        rB1 = *(const uint4*)(pB + (k0) + 8);                           \
    } while (0)

#define STS_CHUNK(buf)                                                  \
    do {                                                                \
        uint32_t* bA = sm + (buf) * BUFU32;                             \
        uint32_t* bB = bA + ARRU32;                                     \
        bA[(kb2 + 0) * SPITCH + r] = rA0.x;                             \
        bA[(kb2 + 1) * SPITCH + r] = rA0.y;                             \
        bA[(kb2 + 2) * SPITCH + r] = rA0.z;                             \
        bA[(kb2 + 3) * SPITCH + r] = rA0.w;                             \
        bA[(kb2 + 4) * SPITCH + r] = rA1.x;                             \
        bA[(kb2 + 5) * SPITCH + r] = rA1.y;                             \
        bA[(kb2 + 6) * SPITCH + r] = rA1.z;                             \
        bA[(kb2 + 7) * SPITCH + r] = rA1.w;                             \
        bB[(kb2 + 0) * SPITCH + r] = rB0.x;                             \
        bB[(kb2 + 1) * SPITCH + r] = rB0.y;                             \
        bB[(kb2 + 2) * SPITCH + r] = rB0.z;                             \
        bB[(kb2 + 3) * SPITCH + r] = rB0.w;                             \
        bB[(kb2 + 4) * SPITCH + r] = rB1.x;                             \
        bB[(kb2 + 5) * SPITCH + r] = rB1.y;                             \
        bB[(kb2 + 6) * SPITCH + r] = rB1.z;                             \
        bB[(kb2 + 7) * SPITCH + r] = rB1.w;                             \
    } while (0)

    const int NC = K / 32;
    LDG_CHUNK(0);
    STS_CHUNK(0);
    __syncthreads();

    for (int c = 0; c < NC; c++) {
        if (c + 1 < NC) LDG_CHUNK((c + 1) * 32);

        const uint32_t* bA = sm + (c & 1) * BUFU32;
        const uint32_t* bB = bA + ARRU32;

        #pragma unroll
        for (int ks = 0; ks < 2; ks++) {
            int kb = ks * 8;
            uint32_t Bf[4][2];
            #pragma unroll
            for (int nt = 0; nt < 4; nt++) {
                int n0 = nb + nt * 8 + gr;
                Bf[nt][0] = bB[(kb + gc) * SPITCH + n0];
                Bf[nt][1] = bB[(kb + gc + 4) * SPITCH + n0];
            }
            #pragma unroll
            for (int mt = 0; mt < 4; mt++) {
                int m0 = mb + mt * 16 + gr;
                uint32_t Af[4];
                Af[0] = bA[(kb + gc) * SPITCH + m0];
                Af[1] = bA[(kb + gc) * SPITCH + m0 + 8];
                Af[2] = bA[(kb + gc + 4) * SPITCH + m0];
                Af[3] = bA[(kb + gc + 4) * SPITCH + m0 + 8];
                #pragma unroll
                for (int nt = 0; nt < 4; nt++)
                    MMA_F16(acc[mt][nt], Af[0], Af[1], Af[2], Af[3],
                            Bf[nt][0], Bf[nt][1]);
            }
        }
        if (c + 1 < NC) STS_CHUNK((c + 1) & 1);
        __syncthreads();
    }

    #pragma unroll
    for (int nt = 0; nt < 4; nt++) {
        int nc = nb + nt * 8 + gc * 2;
        float2 bv = make_float2(bias_s[nc], bias_s[nc + 1]);
        int n0 = bn + nc;
        #pragma unroll
        for (int mt = 0; mt < 4; mt++) {
            int m0 = bm + mb + mt * 16 + gr;
            float v00 = tanhf(acc[mt][nt][0] + bv.x);
            float v01 = tanhf(acc[mt][nt][1] + bv.y);
            float v10 = tanhf(acc[mt][nt][2] + bv.x);
            float v11 = tanhf(acc[mt][nt][3] + bv.y);
            *(__half2*)&C[(size_t)m0 * N + n0] = __floats2half2_rn(v00, v01);
            *(__half2*)&C[(size_t)(m0 + 8) * N + n0] = __floats2half2_rn(v10, v11);
        }
    }
}

// ================= decoder: fp16 gathers, fp32 accum, fused final =================
__global__ void k_decode(const int* __restrict__ tuser, const int* __restrict__ titem,
                         const float* __restrict__ trating,
                         const float* __restrict__ bdec, float* __restrict__ out,
                         int nt, int write_loss) {
    int warp = threadIdx.x >> 5, lane = threadIdx.x & 31;
    int base = blockIdx.x * 32 + warp * 4;
    double mine = 0.0;
    #pragma unroll
    for (int p = 0; p < 2; p++) {
        int t0 = base + p * 2;
        int t1 = t0 + 1;
        bool v0 = t0 < nt, v1 = t1 < nt;
        float s0 = 0.f, s1 = 0.f;
        int u0 = 0, i0 = 0, u1 = 0, i1 = 0;
        if (v0) { u0 = tuser[t0]; i0 = titem[t0]; }
        if (v1) { u1 = tuser[t1]; i1 = titem[t1]; }
        const uint4* ga = (const uint4*)(g_dec + (size_t)u0 * 512);
        const uint4* wa = (const uint4*)(g_wdh + (size_t)i0 * 512);
        const uint4* gb = (const uint4*)(g_dec + (size_t)u1 * 512);
        const uint4* wb = (const uint4*)(g_wdh + (size_t)i1 * 512);
        #pragma unroll
        for (int q = 0; q < 2; q++) {
            if (v0) {
                uint4 a = ga[q * 32 + lane];
                uint4 b = wa[q * 32 + lane];
                float2 f, g;
                f = __half22float2(*(__half2*)&a.x); g = __half22float2(*(__half2*)&b.x);
                s0 = fmaf(f.x, g.x, s0); s0 = fmaf(f.y, g.y, s0);
                f = __half22float2(*(__half2*)&a.y); g = __half22float2(*(__half2*)&b.y);
                s0 = fmaf(f.x, g.x, s0); s0 = fmaf(f.y, g.y, s0);
                f = __half22float2(*(__half2*)&a.z); g = __half22float2(*(__half2*)&b.z);
                s0 = fmaf(f.x, g.x, s0); s0 = fmaf(f.y, g.y, s0);
                f = __half22float2(*(__half2*)&a.w); g = __half22float2(*(__half2*)&b.w);
                s0 = fmaf(f.x, g.x, s0); s0 = fmaf(f.y, g.y, s0);
            }
            if (v1) {
                uint4 a = gb[q * 32 + lane];
                uint4 b = wb[q * 32 + lane];
                float2 f, g;
                f = __half22float2(*(__half2*)&a.x); g = __half22float2(*(__half2*)&b.x);
                s1 = fmaf(f.x, g.x, s1); s1 = fmaf(f.y, g.y, s1);
                f = __half22float2(*(__half2*)&a.y); g = __half22float2(*(__half2*)&b.y);
                s1 = fmaf(f.x, g.x, s1); s1 = fmaf(f.y, g.y, s1);
                f = __half22float2(*(__half2*)&a.z); g = __half22float2(*(__half2*)&b.z);
                s1 = fmaf(f.x, g.x, s1); s1 = fmaf(f.y, g.y, s1);
                f = __half22float2(*(__half2*)&a.w); g = __half22float2(*(__half2*)&b.w);
                s1 = fmaf(f.x, g.x, s1); s1 = fmaf(f.y, g.y, s1);
            }
        }
        #pragma unroll
        for (int o = 16; o; o >>= 1) {
            s0 += __shfl_xor_sync(0xffffffffu, s0, o);
            s1 += __shfl_xor_sync(0xffffffffu, s1, o);
        }
        if (lane == 0) {
            if (v0) {
                float pred = s0 + bdec[i0];
                out[t0] = pred;
                float d = pred - trating[t0];
                mine += (double)d * (double)d;
            }
            if (v1) {
                float pred = s1 + bdec[i1];
                out[t1] = pred;
                float d = pred - trating[t1];
                mine += (double)d * (double)d;
            }
        }
    }
    __shared__ double part_s[8];
    __shared__ int is_last;
    if (lane == 0) part_s[warp] = mine;
    __syncthreads();
    if (threadIdx.x == 0) {
        double ss = 0.0;
        #pragma unroll
        for (int i = 0; i < 8; i++) ss += part_s[i];
        g_part[blockIdx.x] = ss;
        __threadfence();
        int done = atomicAdd(&g_dcount, 1);
        is_last = (done == (int)gridDim.x - 1);
        if (is_last) g_dcount = 0;
    }
    __syncthreads();
    if (is_last) {
        int nb = (int)gridDim.x;
        double s = 0.0;
        for (int i = threadIdx.x; i < nb; i += 256) s += g_part[i];
        __shared__ double red[8];
        #pragma unroll
        for (int o = 16; o; o >>= 1) s += __shfl_xor_sync(0xffffffffu, s, o);
        if (lane == 0) red[warp] = s;
        __syncthreads();
        if (threadIdx.x == 0) {
            double tot = 0.0;
            #pragma unroll
            for (int i = 0; i < 8; i++) tot += red[i];
            if (write_loss) out[nt] = (float)(tot / (double)nt);
        }
    }
}

// ================= launch (forked graph: sort || prep; wdec-convert || encode+GEMMs) ======
extern "C" void kernel_launch(void* const* d_in, const int* in_sizes, int n_in,
                              void* d_out, int out_size) {
    const int*   user    = (const int*)d_in[0];
    const int*   item    = (const int*)d_in[1];
    const float* rating  = (const float*)d_in[2];
    const int*   tuser   = (const int*)d_in[3];
    const int*   titem   = (const int*)d_in[4];
    const float* trating = (const float*)d_in[5];
    const float* W_enc   = (const float*)d_in[6];
    const float* b_enc   = (const float*)d_in[7];
    const float* W1      = (const float*)d_in[8];
    const float* b1      = (const float*)d_in[9];
    const float* W2      = (const float*)d_in[10];
    const float* b2      = (const float*)d_in[11];
    const float* W_dec   = (const float*)d_in[12];
    const float* b_dec   = (const float*)d_in[13];
    float* out = (float*)d_out;

    int N  = in_sizes[0];
    int NT = in_sizes[3];
    (void)n_in;

    void *cnt_ptr, *x_p, *enc_p, *w1_p, *w2_p, *dec_p;
    cudaGetSymbolAddress(&cnt_ptr, g_cnt);
    cudaGetSymbolAddress(&x_p, g_x);
    cudaGetSymbolAddress(&enc_p, g_enc);
    cudaGetSymbolAddress(&w1_p, g_w1);
    cudaGetSymbolAddress(&w2_p, g_w2);
    cudaGetSymbolAddress(&dec_p, g_dec);

    cudaFuncSetAttribute(k_gemm, cudaFuncAttributeMaxDynamicSharedMemorySize, GEMM_SMEM);

    // side streams + events, created once on the (uncaptured) correctness call
    static cudaStream_t s1 = nullptr, s2 = nullptr;
    static cudaEvent_t evA = nullptr, evB = nullptr, ev1 = nullptr, ev2 = nullptr;
    if (!s1) {
        cudaStreamCreateWithFlags(&s1, cudaStreamNonBlocking);
        cudaStreamCreateWithFlags(&s2, cudaStreamNonBlocking);
        cudaEventCreateWithFlags(&evA, cudaEventDisableTiming);
        cudaEventCreateWithFlags(&evB, cudaEventDisableTiming);
        cudaEventCreateWithFlags(&ev1, cudaEventDisableTiming);
        cudaEventCreateWithFlags(&ev2, cudaEventDisableTiming);
    }

    // main stream: zero counters, then fork sort branch
    cudaMemsetAsync(cnt_ptr, 0, NUM_USERS * sizeof(int), 0);
    cudaEventRecord(evA, 0);

    // ---- branch S (s1): counting sort ----
    cudaStreamWaitEvent(s1, evA, 0);
    k_hist<<<(N + 255) / 256, 256, 0, s1>>>(user, N);
    k_scan<<<1, 1024, 0, s1>>>(N);
    k_scatter<<<(N + 255) / 256, 256, 0, s1>>>(user, item, rating, N);
    cudaEventRecord(ev1, s1);

    // ---- main: transpose W_enc + W1/W2 (parallel with sort) ----
    {
        dim3 g((NUM_ITEMS + 31) / 32, 17);
        k_prep_main<<<g, 256>>>(W_enc, W1, W2);
    }
    cudaEventRecord(evB, 0);

    // ---- branch D (s2): Wdec -> fp16 (parallel with encode + GEMMs) ----
    cudaStreamWaitEvent(s2, evB, 0);
    k_prep_wdec<<<(NUM_ITEMS * H0 / 4 + 255) / 256, 256, 0, s2>>>(W_dec);
    cudaEventRecord(ev2, s2);

    // ---- main: join sort, then encode + GEMMs ----
    cudaStreamWaitEvent(0, ev1, 0);
    k_encode<<<NUM_USERS, 128>>>(b_enc);
    {
        dim3 g1(LAT / 128, NUM_USERS / 128);
        k_gemm<<<g1, 256, GEMM_SMEM>>>((const __half*)x_p, (const __half*)w1_p,
                                       b1, (__half*)enc_p, NUM_USERS, LAT, H0);
        dim3 g2(H0 / 128, NUM_USERS / 128);
        k_gemm<<<g2, 256, GEMM_SMEM>>>((const __half*)enc_p, (const __half*)w2_p,
                                       b2, (__half*)dec_p, NUM_USERS, H0, LAT);
    }

    // ---- main: join Wdec branch, then decode + loss ----
    cudaStreamWaitEvent(0, ev2, 0);
    k_decode<<<(NT + 31) / 32, 256>>>(tuser, titem, trating, b_dec, out, NT,
                                      out_size > NT ? 1 : 0);
}